// round 1
// baseline (speedup 1.0000x reference)
#include <cuda_runtime.h>
#include <math.h>

// Problem constants (fixed by setup_inputs)
#define Bn 2
#define Tn 2048
#define NH 16
#define NKV 4
#define HD 128
#define DMODEL 2048
#define KVDIM 512
#define ROWS 4096   // Bn*Tn

// Scratch (allocation-free rule: static __device__ arrays)
__device__ float g_Q[(size_t)ROWS * DMODEL];
__device__ float g_K[(size_t)ROWS * KVDIM];
__device__ float g_V[(size_t)ROWS * KVDIM];
__device__ float g_O[(size_t)ROWS * DMODEL];
__device__ float g_invf[64];

// ---------------------------------------------------------------------------
// invf table: matches reference inv_freq = 10000^(-(2d)/128), computed in double
// ---------------------------------------------------------------------------
__global__ void invf_kernel() {
    int d = threadIdx.x;
    if (d < 64) {
        g_invf[d] = (float)exp(-((double)d / 64.0) * log(10000.0));
    }
}

// ---------------------------------------------------------------------------
// RoPE (GPT-NeoX style, in-place). X: [ROWS, nheads*HD]. Each thread rotates
// one (d, d+64) pair of one head of one row.
// ---------------------------------------------------------------------------
__global__ void rope_kernel(float* __restrict__ X, int nheads, int rowdim, int total) {
    int idx = blockIdx.x * blockDim.x + threadIdx.x;
    if (idx >= total) return;
    int d    = idx & 63;
    int rest = idx >> 6;
    int hh   = rest % nheads;
    int row  = rest / nheads;
    int t    = row & (Tn - 1);   // row % Tn
    float ang = (float)t * g_invf[d];
    float sn, cs;
    sincosf(ang, &sn, &cs);
    float* p = X + (size_t)row * rowdim + hh * HD + d;
    float x0 = p[0], x1 = p[64];
    p[0]  = x0 * cs - x1 * sn;
    p[64] = x1 * cs + x0 * sn;
}

// ---------------------------------------------------------------------------
// fp32 SIMT GEMM: C[M,N] = A[M,K] @ B[K,N], all row-major.
// 128x128 tile, BK=16, 256 threads, 8x8 per thread. M,N,K divisible by tile.
// ---------------------------------------------------------------------------
__global__ __launch_bounds__(256, 2)
void gemm128(const float* __restrict__ A, const float* __restrict__ Bm,
             float* __restrict__ C, int M, int N, int K) {
    __shared__ float As[16][132];   // A tile transposed: As[k][m], padded
    __shared__ float Bs[16][128];   // B tile: Bs[k][n]

    const int tid = threadIdx.x;
    const int tx = tid & 15, ty = tid >> 4;
    const int bx = blockIdx.x, by = blockIdx.y;

    const float* Ablk = A + (size_t)by * 128 * K;
    const float* Bblk = Bm + (size_t)bx * 128;

    float acc[8][8];
#pragma unroll
    for (int i = 0; i < 8; i++)
#pragma unroll
        for (int j = 0; j < 8; j++) acc[i][j] = 0.f;

    for (int k0 = 0; k0 < K; k0 += 16) {
        // Load A tile (128 x 16), store transposed
#pragma unroll
        for (int it = 0; it < 2; it++) {
            int f  = tid + it * 256;       // 0..511 float4 slots
            int r  = f >> 2;               // 4 float4 per row
            int cg = (f & 3) << 2;         // k-offset in floats
            float4 v = *(const float4*)(Ablk + (size_t)r * K + k0 + cg);
            As[cg + 0][r] = v.x; As[cg + 1][r] = v.y;
            As[cg + 2][r] = v.z; As[cg + 3][r] = v.w;
        }
        // Load B tile (16 x 128)
#pragma unroll
        for (int it = 0; it < 2; it++) {
            int f  = tid + it * 256;
            int r  = f >> 5;               // 32 float4 per row
            int cg = (f & 31) << 2;
            *(float4*)(&Bs[r][cg]) = *(const float4*)(Bblk + (size_t)(k0 + r) * N + cg);
        }
        __syncthreads();

#pragma unroll
        for (int k = 0; k < 16; k++) {
            float4 a0 = *(const float4*)(&As[k][ty * 8]);
            float4 a1 = *(const float4*)(&As[k][ty * 8 + 4]);
            float4 b0 = *(const float4*)(&Bs[k][tx * 8]);
            float4 b1 = *(const float4*)(&Bs[k][tx * 8 + 4]);
            float av[8] = {a0.x, a0.y, a0.z, a0.w, a1.x, a1.y, a1.z, a1.w};
            float bv[8] = {b0.x, b0.y, b0.z, b0.w, b1.x, b1.y, b1.z, b1.w};
#pragma unroll
            for (int i = 0; i < 8; i++)
#pragma unroll
                for (int j = 0; j < 8; j++)
                    acc[i][j] += av[i] * bv[j];
        }
        __syncthreads();
    }

    // Write back
#pragma unroll
    for (int i = 0; i < 8; i++) {
        float* cp = C + (size_t)(by * 128 + ty * 8 + i) * N + bx * 128 + tx * 8;
        *(float4*)cp       = make_float4(acc[i][0], acc[i][1], acc[i][2], acc[i][3]);
        *(float4*)(cp + 4) = make_float4(acc[i][4], acc[i][5], acc[i][6], acc[i][7]);
    }
}

// ---------------------------------------------------------------------------
// Causal flash attention, fp32, online softmax.
// Grid: (Tn/64, NH, Bn). Block: 256 threads (16x16).
// Each block: 64 query rows of one (b, h). Loops over key tiles of 64.
// Thread (tx,ty): S-phase owns rows ty*4+r, cols tx+16c (conflict-friendly);
//                 PV-phase owns rows ty*4+r, dv cols tx*8..tx*8+7.
// ---------------------------------------------------------------------------
#define FBM 64
#define FBN 64
#define QSTR 132
#define PSTR 68
#define FLASH_SMEM ((3 * FBM * QSTR + FBM * PSTR) * 4)

__global__ __launch_bounds__(256, 1)
void flash_kernel(const float* __restrict__ Q, const float* __restrict__ Kg,
                  const float* __restrict__ Vg, float* __restrict__ Og) {
    extern __shared__ float sm[];
    float* Qs = sm;
    float* Ks = Qs + FBM * QSTR;
    float* Vs = Ks + FBM * QSTR;
    float* Ps = Vs + FBM * QSTR;

    const int tid = threadIdx.x;
    const int tx = tid & 15, ty = tid >> 4;
    const int qb = blockIdx.x, h = blockIdx.y, b = blockIdx.z;
    const int kvh = h >> 2;  // NH/NKV = 4
    const float scale = 0.08838834764831843f;  // 1/sqrt(128)

    // Load Q tile (64 x 128)
    const float* Qbase = Q + ((size_t)(b * Tn + qb * FBM)) * DMODEL + h * HD;
#pragma unroll
    for (int it = 0; it < 8; it++) {
        int f = tid + it * 256;
        int r = f >> 5;
        int c = (f & 31) << 2;
        *(float4*)(Qs + r * QSTR + c) = *(const float4*)(Qbase + (size_t)r * DMODEL + c);
    }

    float m[4], l[4], o[4][8];
#pragma unroll
    for (int r = 0; r < 4; r++) {
        m[r] = -1e30f; l[r] = 0.f;
#pragma unroll
        for (int c = 0; c < 8; c++) o[r][c] = 0.f;
    }

    const int nkt = qb + 1;   // causal: key tiles 0..qb
    for (int kt = 0; kt < nkt; kt++) {
        __syncthreads();   // previous PV done (and Q tile visible on iter 0)
        const float* Kbase = Kg + ((size_t)(b * Tn + kt * FBN)) * KVDIM + kvh * HD;
        const float* Vbase = Vg + ((size_t)(b * Tn + kt * FBN)) * KVDIM + kvh * HD;
#pragma unroll
        for (int it = 0; it < 8; it++) {
            int f = tid + it * 256;
            int r = f >> 5;
            int c = (f & 31) << 2;
            *(float4*)(Ks + r * QSTR + c) = *(const float4*)(Kbase + (size_t)r * KVDIM + c);
            *(float4*)(Vs + r * QSTR + c) = *(const float4*)(Vbase + (size_t)r * KVDIM + c);
        }
        __syncthreads();

        // ----- S = Q @ K^T -----
        float s[4][4];
#pragma unroll
        for (int r = 0; r < 4; r++)
#pragma unroll
            for (int c = 0; c < 4; c++) s[r][c] = 0.f;

#pragma unroll 4
        for (int d = 0; d < HD; d += 4) {
            float4 q4[4], k4[4];
#pragma unroll
            for (int r = 0; r < 4; r++) q4[r] = *(const float4*)(Qs + (ty * 4 + r) * QSTR + d);
#pragma unroll
            for (int c = 0; c < 4; c++) k4[c] = *(const float4*)(Ks + (tx + 16 * c) * QSTR + d);
#pragma unroll
            for (int r = 0; r < 4; r++)
#pragma unroll
                for (int c = 0; c < 4; c++)
                    s[r][c] += q4[r].x * k4[c].x + q4[r].y * k4[c].y +
                               q4[r].z * k4[c].z + q4[r].w * k4[c].w;
        }

        // scale + causal mask (only diagonal tile needs the mask)
        if (kt == qb) {
#pragma unroll
            for (int r = 0; r < 4; r++) {
                int qrow = ty * 4 + r;
#pragma unroll
                for (int c = 0; c < 4; c++) {
                    int kcol = tx + 16 * c;
                    s[r][c] = (kcol > qrow) ? -1e30f : s[r][c] * scale;
                }
            }
        } else {
#pragma unroll
            for (int r = 0; r < 4; r++)
#pragma unroll
                for (int c = 0; c < 4; c++) s[r][c] *= scale;
        }

        // ----- online softmax (row reductions over 16-lane tx groups) -----
        float alpha[4];
#pragma unroll
        for (int r = 0; r < 4; r++) {
            float tm = fmaxf(fmaxf(s[r][0], s[r][1]), fmaxf(s[r][2], s[r][3]));
#pragma unroll
            for (int off = 8; off > 0; off >>= 1)
                tm = fmaxf(tm, __shfl_xor_sync(0xffffffffu, tm, off));
            float nm = fmaxf(m[r], tm);
            float p0 = __expf(s[r][0] - nm);
            float p1 = __expf(s[r][1] - nm);
            float p2 = __expf(s[r][2] - nm);
            float p3 = __expf(s[r][3] - nm);
            float rs = (p0 + p1) + (p2 + p3);
#pragma unroll
            for (int off = 8; off > 0; off >>= 1)
                rs += __shfl_xor_sync(0xffffffffu, rs, off);
            alpha[r] = __expf(m[r] - nm);
            l[r] = l[r] * alpha[r] + rs;
            m[r] = nm;
            float* pp = Ps + (ty * 4 + r) * PSTR + tx;
            pp[0] = p0; pp[16] = p1; pp[32] = p2; pp[48] = p3;
        }
        __syncthreads();

        // ----- O = O*alpha + P @ V -----
#pragma unroll
        for (int r = 0; r < 4; r++)
#pragma unroll
            for (int c = 0; c < 8; c++) o[r][c] *= alpha[r];

        for (int j = 0; j < FBN; j += 4) {
            float4 pr4[4];
#pragma unroll
            for (int r = 0; r < 4; r++)
                pr4[r] = *(const float4*)(Ps + (ty * 4 + r) * PSTR + j);
#pragma unroll
            for (int jj = 0; jj < 4; jj++) {
                float4 v0 = *(const float4*)(Vs + (j + jj) * QSTR + tx * 8);
                float4 v1 = *(const float4*)(Vs + (j + jj) * QSTR + tx * 8 + 4);
#pragma unroll
                for (int r = 0; r < 4; r++) {
                    float p = ((const float*)&pr4[r])[jj];
                    o[r][0] += p * v0.x; o[r][1] += p * v0.y;
                    o[r][2] += p * v0.z; o[r][3] += p * v0.w;
                    o[r][4] += p * v1.x; o[r][5] += p * v1.y;
                    o[r][6] += p * v1.z; o[r][7] += p * v1.w;
                }
            }
        }
    }

    // Epilogue: O /= l, write to [row, h*HD + dv] layout (ready for @ wo)
    float* Obase = Og + ((size_t)(b * Tn + qb * FBM)) * DMODEL + h * HD;
#pragma unroll
    for (int r = 0; r < 4; r++) {
        float inv = 1.f / l[r];
        float* op = Obase + (size_t)(ty * 4 + r) * DMODEL + tx * 8;
        *(float4*)op       = make_float4(o[r][0] * inv, o[r][1] * inv, o[r][2] * inv, o[r][3] * inv);
        *(float4*)(op + 4) = make_float4(o[r][4] * inv, o[r][5] * inv, o[r][6] * inv, o[r][7] * inv);
    }
}

// ---------------------------------------------------------------------------
// Launch
// ---------------------------------------------------------------------------
extern "C" void kernel_launch(void* const* d_in, const int* in_sizes, int n_in,
                              void* d_out, int out_size) {
    (void)in_sizes; (void)n_in; (void)out_size;
    const float* x  = (const float*)d_in[0];
    const float* wq = (const float*)d_in[1];
    const float* wk = (const float*)d_in[2];
    const float* wv = (const float*)d_in[3];
    const float* wo = (const float*)d_in[4];
    float* out = (float*)d_out;

    float *Q, *K, *V, *O;
    cudaGetSymbolAddress((void**)&Q, g_Q);
    cudaGetSymbolAddress((void**)&K, g_K);
    cudaGetSymbolAddress((void**)&V, g_V);
    cudaGetSymbolAddress((void**)&O, g_O);

    cudaFuncSetAttribute(flash_kernel, cudaFuncAttributeMaxDynamicSharedMemorySize, FLASH_SMEM);

    invf_kernel<<<1, 64>>>();

    // QKV projections
    gemm128<<<dim3(DMODEL / 128, ROWS / 128), 256>>>(x, wq, Q, ROWS, DMODEL, DMODEL);
    gemm128<<<dim3(KVDIM / 128, ROWS / 128), 256>>>(x, wk, K, ROWS, KVDIM, DMODEL);
    gemm128<<<dim3(KVDIM / 128, ROWS / 128), 256>>>(x, wv, V, ROWS, KVDIM, DMODEL);

    // RoPE on Q and K
    {
        int totq = ROWS * NH * 64;
        rope_kernel<<<(totq + 255) / 256, 256>>>(Q, NH, DMODEL, totq);
        int totk = ROWS * NKV * 64;
        rope_kernel<<<(totk + 255) / 256, 256>>>(K, NKV, KVDIM, totk);
    }

    // Causal attention (GQA handled by kvh = h/4 inside)
    flash_kernel<<<dim3(Tn / FBM, NH, Bn), 256, FLASH_SMEM>>>(Q, K, V, O);

    // Output projection
    gemm128<<<dim3(DMODEL / 128, ROWS / 128), 256>>>(O, wo, out, ROWS, DMODEL, DMODEL);
}

// round 3
// speedup vs baseline: 1.7724x; 1.7724x over previous
#include <cuda_runtime.h>
#include <math.h>
#include <stdint.h>

// ---------------- problem constants ----------------
#define Bn 2
#define Tn 2048
#define NH 16
#define NKV 4
#define HD 128
#define DMODEL 2048
#define KVDIM 512
#define KVSTR 1024          // combined KV row stride (K cols 0..511, V cols 512..1023)
#define ROWS 4096           // Bn*Tn
#define GK 2048             // K dim of every GEMM

// ---------------- scratch (__device__ globals) ----------------
__device__ float g_xr[(size_t)ROWS * DMODEL];   // tf32-rounded x
__device__ float g_Q [(size_t)ROWS * DMODEL];
__device__ float g_KV[(size_t)ROWS * KVSTR];
__device__ float g_O [(size_t)ROWS * DMODEL];   // flash output, tf32-rounded
__device__ float g_wqT [(size_t)DMODEL * GK];   // [N,K] K-major, tf32-rounded
__device__ float g_wkvT[(size_t)KVSTR  * GK];
__device__ float g_woT [(size_t)DMODEL * GK];
__device__ float g_invf[64];

// ---------------- PTX helpers (baseline sm_80+ only) ----------------
__device__ __forceinline__ uint32_t smem_u32(const void* p) {
    uint32_t a;
    asm("{ .reg .u64 t; cvta.to.shared.u64 t, %1; cvt.u32.u64 %0, t; }" : "=r"(a) : "l"(p));
    return a;
}
__device__ __forceinline__ uint32_t f2tf32(float x) {
    uint32_t r; asm("cvt.rna.tf32.f32 %0, %1;" : "=r"(r) : "f"(x)); return r;
}
__device__ __forceinline__ uint32_t swz(uint32_t off) {   // SW128: xor bits[6:4] ^= bits[9:7]
    return off ^ ((off >> 3) & 0x70);
}
__device__ __forceinline__ void cp16(uint32_t dst, const void* src) {
    asm volatile("cp.async.cg.shared.global [%0], [%1], 16;" :: "r"(dst), "l"(src) : "memory");
}
#define CP_COMMIT() asm volatile("cp.async.commit_group;" ::: "memory")
#define CP_WAIT(n)  asm volatile("cp.async.wait_group %0;" :: "n"(n) : "memory")

__device__ __forceinline__ void ldsm_x4(uint32_t* r, uint32_t addr) {
    asm volatile("ldmatrix.sync.aligned.m8n8.x4.shared.b16 {%0,%1,%2,%3}, [%4];"
                 : "=r"(r[0]), "=r"(r[1]), "=r"(r[2]), "=r"(r[3]) : "r"(addr));
}
__device__ __forceinline__ void mma_tf32(float* d, const uint32_t* a, const uint32_t* b) {
    asm volatile(
        "mma.sync.aligned.m16n8k8.row.col.f32.tf32.tf32.f32 "
        "{%0,%1,%2,%3}, {%4,%5,%6,%7}, {%8,%9}, {%0,%1,%2,%3};"
        : "+f"(d[0]), "+f"(d[1]), "+f"(d[2]), "+f"(d[3])
        : "r"(a[0]), "r"(a[1]), "r"(a[2]), "r"(a[3]), "r"(b[0]), "r"(b[1]));
}

// ---------------- misc small kernels ----------------
__global__ void invf_kernel() {
    int d = threadIdx.x;
    if (d < 64) g_invf[d] = (float)exp(-((double)d / 64.0) * log(10000.0));
}

// out[n*K + k] = round_tf32(in[k*N + n]);  grid (N/32, K/32), block (32,8)
__global__ void transpose_rna(const float* __restrict__ in, float* __restrict__ out, int K, int N) {
    __shared__ float t[32][33];
    int n0 = blockIdx.x * 32, k0 = blockIdx.y * 32;
#pragma unroll
    for (int i = threadIdx.y; i < 32; i += 8)
        t[i][threadIdx.x] = in[(size_t)(k0 + i) * N + n0 + threadIdx.x];
    __syncthreads();
#pragma unroll
    for (int i = threadIdx.y; i < 32; i += 8)
        out[(size_t)(n0 + i) * K + k0 + threadIdx.x] = __uint_as_float(f2tf32(t[threadIdx.x][i]));
}

// elementwise tf32 rounding, vectorized
__global__ void round_rna_vec(const float* __restrict__ in, float* __restrict__ out, int n4) {
    int i = blockIdx.x * blockDim.x + threadIdx.x;
    if (i < n4) {
        float4 v = ((const float4*)in)[i];
        uint4 r = make_uint4(f2tf32(v.x), f2tf32(v.y), f2tf32(v.z), f2tf32(v.w));
        ((uint4*)out)[i] = r;
    }
}

__global__ void rope_kernel(float* __restrict__ X, int nheads, int rowdim, int total) {
    int idx = blockIdx.x * blockDim.x + threadIdx.x;
    if (idx >= total) return;
    int d    = idx & 63;
    int rest = idx >> 6;
    int hh   = rest % nheads;
    int row  = rest / nheads;
    int t    = row & (Tn - 1);
    float ang = (float)t * g_invf[d];
    float sn, cs;
    sincosf(ang, &sn, &cs);
    float* p = X + (size_t)row * rowdim + hh * HD + d;
    float x0 = p[0], x1 = p[64];
    p[0]  = x0 * cs - x1 * sn;
    p[64] = x1 * cs + x0 * sn;
}

// ---------------- tf32 mma.sync GEMM ----------------
// C[M,N] = A[M,2048] @ Bt[N,2048]^T.  A,Bt pre-rounded tf32, K-major.
// Block 128x128, BK=32, 4-stage cp.async pipeline, 8 warps (2x4), warp tile 64x32.
#define BM 128
#define BN 128
#define BK 32
#define NSTG 4
#define ASTG 16384            // 128 rows x 128B
#define BSTG 16384
#define STG  (ASTG + BSTG)
#define GEMM_SMEM (NSTG * STG)
#define KITERS (GK / BK)      // 64

__global__ __launch_bounds__(256, 1)
void gemm_mma(const float* __restrict__ A, const float* __restrict__ Bt,
              float* __restrict__ C, int N) {
    extern __shared__ char dsm[];
    const uint32_t base = smem_u32(dsm);

    const int tid  = threadIdx.x;
    const int wid  = tid >> 5;
    const int lane = tid & 31;
    const int mb   = blockIdx.y * BM;
    const int nb   = blockIdx.x * BN;
    const int wm   = (wid & 1) * 64;   // warp row offset
    const int wn   = (wid >> 1) * 32;  // warp col offset

    const float* Ag = A  + (size_t)mb * GK;
    const float* Bg = Bt + (size_t)nb * GK;

    float acc[4][4][4];
#pragma unroll
    for (int mt = 0; mt < 4; mt++)
#pragma unroll
        for (int nt = 0; nt < 4; nt++)
#pragma unroll
            for (int q = 0; q < 4; q++) acc[mt][nt][q] = 0.f;

    // per-thread cp.async mapping: chunk cc -> row=cc>>3, kc=cc&7 (16B chunks)
    auto issue = [&](int s) {
        uint32_t sa = base + (s & (NSTG - 1)) * STG;
        uint32_t sbm = sa + ASTG;
        int k0 = s * BK;
#pragma unroll
        for (int i = 0; i < 4; i++) {
            int cc  = tid + i * 256;
            int row = cc >> 3, kc = cc & 7;
            uint32_t off = swz((uint32_t)(row * 128 + kc * 16));
            cp16(sa  + off, Ag + (size_t)row * GK + k0 + kc * 4);
            cp16(sbm + off, Bg + (size_t)row * GK + k0 + kc * 4);
        }
        CP_COMMIT();
    };

    issue(0); issue(1); issue(2);

    // ldmatrix lane address components (constant per thread)
    const int a_r  = (lane & 7) + ((lane >> 3) & 1) * 8;  // A row within m16
    const int a_kc = (lane >> 4);                          // A kchunk bit
    const int b_r  = (lane & 7) + (lane >> 4) * 8;         // B row within n16
    const int b_kc = ((lane >> 3) & 1);                    // B kchunk bit

    for (int s = 0; s < KITERS; s++) {
        CP_WAIT(2);
        __syncthreads();
        if (s + 3 < KITERS) issue(s + 3);

        uint32_t sa = base + (s & (NSTG - 1)) * STG + (uint32_t)(wm * 128);
        uint32_t sb = base + (s & (NSTG - 1)) * STG + ASTG + (uint32_t)(wn * 128);

#pragma unroll
        for (int ks = 0; ks < 4; ks++) {
            uint32_t afr[4][4];
            uint32_t bfr[4][2];
#pragma unroll
            for (int mt = 0; mt < 4; mt++) {
                uint32_t addr = sa + swz((uint32_t)((mt * 16 + a_r) * 128 + (2 * ks + a_kc) * 16));
                ldsm_x4(afr[mt], addr);
            }
#pragma unroll
            for (int np = 0; np < 2; np++) {
                uint32_t tmp[4];
                uint32_t addr = sb + swz((uint32_t)((np * 16 + b_r) * 128 + (2 * ks + b_kc) * 16));
                ldsm_x4(tmp, addr);
                bfr[np * 2][0] = tmp[0]; bfr[np * 2][1] = tmp[1];
                bfr[np * 2 + 1][0] = tmp[2]; bfr[np * 2 + 1][1] = tmp[3];
            }
#pragma unroll
            for (int mt = 0; mt < 4; mt++)
#pragma unroll
                for (int nt = 0; nt < 4; nt++)
                    mma_tf32(acc[mt][nt], afr[mt], bfr[nt]);
        }
        __syncthreads();
    }

    // Epilogue
    const int g = lane >> 2;
    const int cq = (lane & 3) * 2;
#pragma unroll
    for (int mt = 0; mt < 4; mt++) {
        int row0 = mb + wm + mt * 16 + g;
#pragma unroll
        for (int nt = 0; nt < 4; nt++) {
            int col = nb + wn + nt * 8 + cq;
            *(float2*)(C + (size_t)row0 * N + col)       = make_float2(acc[mt][nt][0], acc[mt][nt][1]);
            *(float2*)(C + (size_t)(row0 + 8) * N + col) = make_float2(acc[mt][nt][2], acc[mt][nt][3]);
        }
    }
}

// ---------------- flash attention (fp32 SIMT; epilogue rounds to tf32) ------
#define FBM 64
#define FBN 64
#define QSTR 132
#define PSTR 68
#define FLASH_SMEM ((3 * FBM * QSTR + FBM * PSTR) * 4)

__global__ __launch_bounds__(256, 1)
void flash_kernel(const float* __restrict__ Q, const float* __restrict__ KV,
                  float* __restrict__ Og) {
    extern __shared__ float sm[];
    float* Qs = sm;
    float* Ks = Qs + FBM * QSTR;
    float* Vs = Ks + FBM * QSTR;
    float* Ps = Vs + FBM * QSTR;

    const int tid = threadIdx.x;
    const int tx = tid & 15, ty = tid >> 4;
    const int qb = blockIdx.x, h = blockIdx.y, b = blockIdx.z;
    const int kvh = h >> 2;
    const float scale = 0.08838834764831843f;

    const float* Qbase = Q + ((size_t)(b * Tn + qb * FBM)) * DMODEL + h * HD;
#pragma unroll
    for (int it = 0; it < 8; it++) {
        int f = tid + it * 256;
        int r = f >> 5;
        int c = (f & 31) << 2;
        *(float4*)(Qs + r * QSTR + c) = *(const float4*)(Qbase + (size_t)r * DMODEL + c);
    }

    float m[4], l[4], o[4][8];
#pragma unroll
    for (int r = 0; r < 4; r++) {
        m[r] = -1e30f; l[r] = 0.f;
#pragma unroll
        for (int c = 0; c < 8; c++) o[r][c] = 0.f;
    }

    const int nkt = qb + 1;
    for (int kt = 0; kt < nkt; kt++) {
        __syncthreads();
        const float* Kbase = KV + ((size_t)(b * Tn + kt * FBN)) * KVSTR + kvh * HD;
        const float* Vbase = Kbase + 512;
#pragma unroll
        for (int it = 0; it < 8; it++) {
            int f = tid + it * 256;
            int r = f >> 5;
            int c = (f & 31) << 2;
            *(float4*)(Ks + r * QSTR + c) = *(const float4*)(Kbase + (size_t)r * KVSTR + c);
            *(float4*)(Vs + r * QSTR + c) = *(const float4*)(Vbase + (size_t)r * KVSTR + c);
        }
        __syncthreads();

        float s[4][4];
#pragma unroll
        for (int r = 0; r < 4; r++)
#pragma unroll
            for (int c = 0; c < 4; c++) s[r][c] = 0.f;

#pragma unroll 4
        for (int d = 0; d < HD; d += 4) {
            float4 q4[4], k4[4];
#pragma unroll
            for (int r = 0; r < 4; r++) q4[r] = *(const float4*)(Qs + (ty * 4 + r) * QSTR + d);
#pragma unroll
            for (int c = 0; c < 4; c++) k4[c] = *(const float4*)(Ks + (tx + 16 * c) * QSTR + d);
#pragma unroll
            for (int r = 0; r < 4; r++)
#pragma unroll
                for (int c = 0; c < 4; c++)
                    s[r][c] += q4[r].x * k4[c].x + q4[r].y * k4[c].y +
                               q4[r].z * k4[c].z + q4[r].w * k4[c].w;
        }

        if (kt == qb) {
#pragma unroll
            for (int r = 0; r < 4; r++) {
                int qrow = ty * 4 + r;
#pragma unroll
                for (int c = 0; c < 4; c++) {
                    int kcol = tx + 16 * c;
                    s[r][c] = (kcol > qrow) ? -1e30f : s[r][c] * scale;
                }
            }
        } else {
#pragma unroll
            for (int r = 0; r < 4; r++)
#pragma unroll
                for (int c = 0; c < 4; c++) s[r][c] *= scale;
        }

        float alpha[4];
#pragma unroll
        for (int r = 0; r < 4; r++) {
            float tm = fmaxf(fmaxf(s[r][0], s[r][1]), fmaxf(s[r][2], s[r][3]));
#pragma unroll
            for (int off = 8; off > 0; off >>= 1)
                tm = fmaxf(tm, __shfl_xor_sync(0xffffffffu, tm, off));
            float nm = fmaxf(m[r], tm);
            float p0 = __expf(s[r][0] - nm);
            float p1 = __expf(s[r][1] - nm);
            float p2 = __expf(s[r][2] - nm);
            float p3 = __expf(s[r][3] - nm);
            float rs = (p0 + p1) + (p2 + p3);
#pragma unroll
            for (int off = 8; off > 0; off >>= 1)
                rs += __shfl_xor_sync(0xffffffffu, rs, off);
            alpha[r] = __expf(m[r] - nm);
            l[r] = l[r] * alpha[r] + rs;
            m[r] = nm;
            float* pp = Ps + (ty * 4 + r) * PSTR + tx;
            pp[0] = p0; pp[16] = p1; pp[32] = p2; pp[48] = p3;
        }
        __syncthreads();

#pragma unroll
        for (int r = 0; r < 4; r++)
#pragma unroll
            for (int c = 0; c < 8; c++) o[r][c] *= alpha[r];

        for (int j = 0; j < FBN; j += 4) {
            float4 pr4[4];
#pragma unroll
            for (int r = 0; r < 4; r++)
                pr4[r] = *(const float4*)(Ps + (ty * 4 + r) * PSTR + j);
#pragma unroll
            for (int jj = 0; jj < 4; jj++) {
                float4 v0 = *(const float4*)(Vs + (j + jj) * QSTR + tx * 8);
                float4 v1 = *(const float4*)(Vs + (j + jj) * QSTR + tx * 8 + 4);
#pragma unroll
                for (int r = 0; r < 4; r++) {
                    float p = ((const float*)&pr4[r])[jj];
                    o[r][0] += p * v0.x; o[r][1] += p * v0.y;
                    o[r][2] += p * v0.z; o[r][3] += p * v0.w;
                    o[r][4] += p * v1.x; o[r][5] += p * v1.y;
                    o[r][6] += p * v1.z; o[r][7] += p * v1.w;
                }
            }
        }
    }

    // Epilogue: O /= l, round to tf32 (feeds the tf32 output projection)
    float* Obase = Og + ((size_t)(b * Tn + qb * FBM)) * DMODEL + h * HD;
#pragma unroll
    for (int r = 0; r < 4; r++) {
        float inv = 1.f / l[r];
        float* op = Obase + (size_t)(ty * 4 + r) * DMODEL + tx * 8;
        uint4 w0 = make_uint4(f2tf32(o[r][0] * inv), f2tf32(o[r][1] * inv),
                              f2tf32(o[r][2] * inv), f2tf32(o[r][3] * inv));
        uint4 w1 = make_uint4(f2tf32(o[r][4] * inv), f2tf32(o[r][5] * inv),
                              f2tf32(o[r][6] * inv), f2tf32(o[r][7] * inv));
        *(uint4*)op       = w0;
        *(uint4*)(op + 4) = w1;
    }
}

// ---------------- launch ----------------
extern "C" void kernel_launch(void* const* d_in, const int* in_sizes, int n_in,
                              void* d_out, int out_size) {
    (void)in_sizes; (void)n_in; (void)out_size;
    const float* x  = (const float*)d_in[0];
    const float* wq = (const float*)d_in[1];
    const float* wk = (const float*)d_in[2];
    const float* wv = (const float*)d_in[3];
    const float* wo = (const float*)d_in[4];
    float* out = (float*)d_out;

    float *xr, *Q, *KV, *O, *wqT, *wkvT, *woT;
    cudaGetSymbolAddress((void**)&xr,   g_xr);
    cudaGetSymbolAddress((void**)&Q,    g_Q);
    cudaGetSymbolAddress((void**)&KV,   g_KV);
    cudaGetSymbolAddress((void**)&O,    g_O);
    cudaGetSymbolAddress((void**)&wqT,  g_wqT);
    cudaGetSymbolAddress((void**)&wkvT, g_wkvT);
    cudaGetSymbolAddress((void**)&woT,  g_woT);

    cudaFuncSetAttribute(flash_kernel, cudaFuncAttributeMaxDynamicSharedMemorySize, FLASH_SMEM);
    cudaFuncSetAttribute(gemm_mma,     cudaFuncAttributeMaxDynamicSharedMemorySize, GEMM_SMEM);

    invf_kernel<<<1, 64>>>();

    // Weights: transpose to [N,K] K-major + tf32 rounding
    transpose_rna<<<dim3(DMODEL / 32, GK / 32), dim3(32, 8)>>>(wq, wqT, GK, DMODEL);
    transpose_rna<<<dim3(KVDIM  / 32, GK / 32), dim3(32, 8)>>>(wk, wkvT, GK, KVDIM);
    transpose_rna<<<dim3(KVDIM  / 32, GK / 32), dim3(32, 8)>>>(wv, wkvT + (size_t)KVDIM * GK, GK, KVDIM);
    transpose_rna<<<dim3(DMODEL / 32, GK / 32), dim3(32, 8)>>>(wo, woT, GK, DMODEL);

    // Activations: tf32 rounding
    {
        int n4 = ROWS * DMODEL / 4;
        round_rna_vec<<<(n4 + 255) / 256, 256>>>(x, xr, n4);
    }

    // Projections on legacy tensor cores (mma.sync tf32)
    gemm_mma<<<dim3(DMODEL / BN, ROWS / BM), 256, GEMM_SMEM>>>(xr, wqT,  Q,  DMODEL);
    gemm_mma<<<dim3(KVSTR  / BN, ROWS / BM), 256, GEMM_SMEM>>>(xr, wkvT, KV, KVSTR);

    // RoPE on Q and K (K = first 512 cols of KV)
    {
        int totq = ROWS * NH * 64;
        rope_kernel<<<(totq + 255) / 256, 256>>>(Q, NH, DMODEL, totq);
        int totk = ROWS * NKV * 64;
        rope_kernel<<<(totk + 255) / 256, 256>>>(KV, NKV, KVSTR, totk);
    }

    // Causal attention (writes tf32-rounded O)
    flash_kernel<<<dim3(Tn / FBM, NH, Bn), 256, FLASH_SMEM>>>(Q, KV, O);

    // Output projection
    gemm_mma<<<dim3(DMODEL / BN, ROWS / BM), 256, GEMM_SMEM>>>(O, woT, out, DMODEL);
}

// round 4
// speedup vs baseline: 3.5699x; 2.0141x over previous
#include <cuda_runtime.h>
#include <math.h>
#include <stdint.h>

// ---------------- problem constants ----------------
#define Bn 2
#define Tn 2048
#define NH 16
#define NKV 4
#define HD 128
#define DMODEL 2048
#define KVDIM 512
#define KVSTR 1024          // combined KV row stride (K cols 0..511, V cols 512..1023)
#define ROWS 4096           // Bn*Tn
#define GK 2048             // K dim of every GEMM

// ---------------- scratch (__device__ globals) ----------------
__device__ float g_xr[(size_t)ROWS * DMODEL];   // tf32-rounded x
__device__ float g_Q [(size_t)ROWS * DMODEL];
__device__ float g_KV[(size_t)ROWS * KVSTR];
__device__ float g_VT[(size_t)ROWS * KVDIM];    // V transposed: [b][kvh][d][t], tf32-rounded
__device__ float g_O [(size_t)ROWS * DMODEL];   // flash output, tf32-rounded
__device__ float g_wqT [(size_t)DMODEL * GK];   // [N,K] K-major, tf32-rounded
__device__ float g_wkvT[(size_t)KVSTR  * GK];
__device__ float g_woT [(size_t)DMODEL * GK];
__device__ float g_invf[64];

// ---------------- PTX helpers (baseline sm_80+ only) ----------------
__device__ __forceinline__ uint32_t smem_u32(const void* p) {
    uint32_t a;
    asm("{ .reg .u64 t; cvta.to.shared.u64 t, %1; cvt.u32.u64 %0, t; }" : "=r"(a) : "l"(p));
    return a;
}
__device__ __forceinline__ uint32_t f2tf32(float x) {
    uint32_t r; asm("cvt.rna.tf32.f32 %0, %1;" : "=r"(r) : "f"(x)); return r;
}
__device__ __forceinline__ uint32_t swz(uint32_t off) {   // SW128: bits[6:4] ^= bits[9:7]
    return off ^ ((off >> 3) & 0x70);
}
__device__ __forceinline__ void cp16(uint32_t dst, const void* src) {
    asm volatile("cp.async.cg.shared.global [%0], [%1], 16;" :: "r"(dst), "l"(src) : "memory");
}
#define CP_COMMIT() asm volatile("cp.async.commit_group;" ::: "memory")
#define CP_WAIT(n)  asm volatile("cp.async.wait_group %0;" :: "n"(n) : "memory")

__device__ __forceinline__ void ldsm_x4(uint32_t* r, uint32_t addr) {
    asm volatile("ldmatrix.sync.aligned.m8n8.x4.shared.b16 {%0,%1,%2,%3}, [%4];"
                 : "=r"(r[0]), "=r"(r[1]), "=r"(r[2]), "=r"(r[3]) : "r"(addr));
}
__device__ __forceinline__ void mma_tf32(float* d, const uint32_t* a, const uint32_t* b) {
    asm volatile(
        "mma.sync.aligned.m16n8k8.row.col.f32.tf32.tf32.f32 "
        "{%0,%1,%2,%3}, {%4,%5,%6,%7}, {%8,%9}, {%0,%1,%2,%3};"
        : "+f"(d[0]), "+f"(d[1]), "+f"(d[2]), "+f"(d[3])
        : "r"(a[0]), "r"(a[1]), "r"(a[2]), "r"(a[3]), "r"(b[0]), "r"(b[1]));
}
#define STS128(r0, r1, r2, r3, smem_addr) \
    asm volatile("st.shared.v4.b32 [%0], {%1, %2, %3, %4};" \
        :: "r"(smem_addr), "r"(r0), "r"(r1), "r"(r2), "r"(r3) : "memory")
__device__ __forceinline__ void sts64(uint32_t addr, uint32_t a, uint32_t b) {
    asm volatile("st.shared.v2.b32 [%0], {%1,%2};" :: "r"(addr), "r"(a), "r"(b) : "memory");
}

// ---------------- misc small kernels ----------------
__global__ void invf_kernel() {
    int d = threadIdx.x;
    if (d < 64) g_invf[d] = (float)exp(-((double)d / 64.0) * log(10000.0));
}

// out[n*K + k] = round_tf32(in[k*N + n]);  grid (N/32, K/32), block (32,8)
__global__ void transpose_rna(const float* __restrict__ in, float* __restrict__ out, int K, int N) {
    __shared__ float t[32][33];
    int n0 = blockIdx.x * 32, k0 = blockIdx.y * 32;
#pragma unroll
    for (int i = threadIdx.y; i < 32; i += 8)
        t[i][threadIdx.x] = in[(size_t)(k0 + i) * N + n0 + threadIdx.x];
    __syncthreads();
#pragma unroll
    for (int i = threadIdx.y; i < 32; i += 8)
        out[(size_t)(n0 + i) * K + k0 + threadIdx.x] = __uint_as_float(f2tf32(t[threadIdx.x][i]));
}

// V transpose: g_KV V-half [b*Tn+t][512 + kvh*HD + d] -> g_VT[(b*NKV+kvh)*HD + d][t]
// grid (Tn/32, HD/32, Bn*NKV), block (32,8)
__global__ void vtrans_kernel(const float* __restrict__ KV, float* __restrict__ VT) {
    __shared__ float t[32][33];
    int bk = blockIdx.z;
    int b = bk >> 2, kvh = bk & 3;
    const float* src = KV + ((size_t)b * Tn) * KVSTR + 512 + kvh * HD;
    float* dst = VT + (size_t)bk * HD * Tn;
    int t0 = blockIdx.x * 32, d0 = blockIdx.y * 32;
#pragma unroll
    for (int i = threadIdx.y; i < 32; i += 8)
        t[i][threadIdx.x] = src[(size_t)(t0 + i) * KVSTR + d0 + threadIdx.x];
    __syncthreads();
#pragma unroll
    for (int i = threadIdx.y; i < 32; i += 8)
        dst[(size_t)(d0 + i) * Tn + t0 + threadIdx.x] = __uint_as_float(f2tf32(t[threadIdx.x][i]));
}

// elementwise tf32 rounding, vectorized
__global__ void round_rna_vec(const float* __restrict__ in, float* __restrict__ out, int n4) {
    int i = blockIdx.x * blockDim.x + threadIdx.x;
    if (i < n4) {
        float4 v = ((const float4*)in)[i];
        uint4 r = make_uint4(f2tf32(v.x), f2tf32(v.y), f2tf32(v.z), f2tf32(v.w));
        ((uint4*)out)[i] = r;
    }
}

// RoPE in-place; outputs tf32-rounded (feeds tensor-core matmuls)
__global__ void rope_kernel(float* __restrict__ X, int nheads, int rowdim, int total) {
    int idx = blockIdx.x * blockDim.x + threadIdx.x;
    if (idx >= total) return;
    int d    = idx & 63;
    int rest = idx >> 6;
    int hh   = rest % nheads;
    int row  = rest / nheads;
    int t    = row & (Tn - 1);
    float ang = (float)t * g_invf[d];
    float sn, cs;
    sincosf(ang, &sn, &cs);
    float* p = X + (size_t)row * rowdim + hh * HD + d;
    float x0 = p[0], x1 = p[64];
    p[0]  = __uint_as_float(f2tf32(x0 * cs - x1 * sn));
    p[64] = __uint_as_float(f2tf32(x1 * cs + x0 * sn));
}

// ---------------- tf32 mma.sync GEMM (unchanged from R3) ----------------
#define BM 128
#define BN 128
#define BK 32
#define NSTG 4
#define ASTG 16384
#define BSTG 16384
#define STG  (ASTG + BSTG)
#define GEMM_SMEM (NSTG * STG)
#define KITERS (GK / BK)

__global__ __launch_bounds__(256, 1)
void gemm_mma(const float* __restrict__ A, const float* __restrict__ Bt,
              float* __restrict__ C, int N) {
    extern __shared__ char dsm[];
    const uint32_t base = smem_u32(dsm);

    const int tid  = threadIdx.x;
    const int wid  = tid >> 5;
    const int lane = tid & 31;
    const int mb   = blockIdx.y * BM;
    const int nb   = blockIdx.x * BN;
    const int wm   = (wid & 1) * 64;
    const int wn   = (wid >> 1) * 32;

    const float* Ag = A  + (size_t)mb * GK;
    const float* Bg = Bt + (size_t)nb * GK;

    float acc[4][4][4];
#pragma unroll
    for (int mt = 0; mt < 4; mt++)
#pragma unroll
        for (int nt = 0; nt < 4; nt++)
#pragma unroll
            for (int q = 0; q < 4; q++) acc[mt][nt][q] = 0.f;

    auto issue = [&](int s) {
        uint32_t sa = base + (s & (NSTG - 1)) * STG;
        uint32_t sbm = sa + ASTG;
        int k0 = s * BK;
#pragma unroll
        for (int i = 0; i < 4; i++) {
            int cc  = tid + i * 256;
            int row = cc >> 3, kc = cc & 7;
            uint32_t off = swz((uint32_t)(row * 128 + kc * 16));
            cp16(sa  + off, Ag + (size_t)row * GK + k0 + kc * 4);
            cp16(sbm + off, Bg + (size_t)row * GK + k0 + kc * 4);
        }
        CP_COMMIT();
    };

    issue(0); issue(1); issue(2);

    const int a_r  = (lane & 7) + ((lane >> 3) & 1) * 8;
    const int a_kc = (lane >> 4);
    const int b_r  = (lane & 7) + (lane >> 4) * 8;
    const int b_kc = ((lane >> 3) & 1);

    for (int s = 0; s < KITERS; s++) {
        CP_WAIT(2);
        __syncthreads();
        if (s + 3 < KITERS) issue(s + 3);

        uint32_t sa = base + (s & (NSTG - 1)) * STG + (uint32_t)(wm * 128);
        uint32_t sb = base + (s & (NSTG - 1)) * STG + ASTG + (uint32_t)(wn * 128);

#pragma unroll
        for (int ks = 0; ks < 4; ks++) {
            uint32_t afr[4][4];
            uint32_t bfr[4][2];
#pragma unroll
            for (int mt = 0; mt < 4; mt++) {
                uint32_t addr = sa + swz((uint32_t)((mt * 16 + a_r) * 128 + (2 * ks + a_kc) * 16));
                ldsm_x4(afr[mt], addr);
            }
#pragma unroll
            for (int np = 0; np < 2; np++) {
                uint32_t tmp[4];
                uint32_t addr = sb + swz((uint32_t)((np * 16 + b_r) * 128 + (2 * ks + b_kc) * 16));
                ldsm_x4(tmp, addr);
                bfr[np * 2][0] = tmp[0]; bfr[np * 2][1] = tmp[1];
                bfr[np * 2 + 1][0] = tmp[2]; bfr[np * 2 + 1][1] = tmp[3];
            }
#pragma unroll
            for (int mt = 0; mt < 4; mt++)
#pragma unroll
                for (int nt = 0; nt < 4; nt++)
                    mma_tf32(acc[mt][nt], afr[mt], bfr[nt]);
        }
        __syncthreads();
    }

    const int g = lane >> 2;
    const int cq = (lane & 3) * 2;
#pragma unroll
    for (int mt = 0; mt < 4; mt++) {
        int row0 = mb + wm + mt * 16 + g;
#pragma unroll
        for (int nt = 0; nt < 4; nt++) {
            int col = nb + wn + nt * 8 + cq;
            *(float2*)(C + (size_t)row0 * N + col)       = make_float2(acc[mt][nt][0], acc[mt][nt][1]);
            *(float2*)(C + (size_t)(row0 + 8) * N + col) = make_float2(acc[mt][nt][2], acc[mt][nt][3]);
        }
    }
}

// ---------------- flash attention on mma.sync tf32 ----------------
// CTA: 128 q-rows of one (b,h); 8 warps x 16 rows. Key tiles of 64, K/V double-
// buffered via cp.async. Smem layout (column-chunk-major, 128B sub-rows, swz):
//   Qs [dc(4)][qrow(128)][32f]  @ 0       (64KB)
//   Ks [dc(4)][key(64)][32f]    @ 65536 + buf*65536  (32KB each)
//   Vt [kc(2)][d(128)][32f]     @ Ks + 32768
//   Ps [kc(2)][qrow(128)][32f]  @ 196608  (32KB)
#define FM 128
#define FN 64
#define FLASH_SMEM 229376

__global__ __launch_bounds__(256, 1)
void flash_mma(const float* __restrict__ Q, const float* __restrict__ KV,
               const float* __restrict__ VT, float* __restrict__ Og) {
    extern __shared__ float sm[];
    const uint32_t base = smem_u32(sm);
    const int tid = threadIdx.x, wid = tid >> 5, lane = tid & 31;
    const int qb = (Tn / FM - 1) - blockIdx.x;   // heavy blocks first
    const int h = blockIdx.y, b = blockIdx.z;
    const int kvh = h >> 2;
    const int nkt = 2 * qb + 2;

    const float* Qg  = Q  + ((size_t)(b * Tn + qb * FM)) * DMODEL + h * HD;
    const float* Kg  = KV + ((size_t)(b * Tn)) * KVSTR + kvh * HD;
    const float* Vtg = VT + ((size_t)(b * NKV + kvh)) * HD * Tn;

    // ---- load Q tile (128 x 128): warp w writes q-rows w+8i, full 128B rows
#pragma unroll
    for (int i = 0; i < 16; i++) {
        int f = tid + i * 256;
        int qr = f >> 5, dq = f & 31;
        float4 v = *(const float4*)(Qg + (size_t)qr * DMODEL + dq * 4);
        uint32_t off = swz((uint32_t)(((dq >> 3) * 128 + qr) * 128 + (dq & 7) * 16));
        STS128(__float_as_uint(v.x), __float_as_uint(v.y),
               __float_as_uint(v.z), __float_as_uint(v.w), base + off);
    }

    auto kv_issue = [&](int kt) {
        uint32_t kb = base + 65536u + (uint32_t)(kt & 1) * 65536u;
        uint32_t vb = kb + 32768u;
        const float* Ksrc = Kg  + (size_t)(kt * FN) * KVSTR;
        const float* Vsrc = Vtg + kt * FN;
#pragma unroll
        for (int i = 0; i < 8; i++) {
            int f = tid + i * 256;
            int kr = f >> 5, dq = f & 31;
            cp16(kb + swz((uint32_t)(((dq >> 3) * 64 + kr) * 128 + (dq & 7) * 16)),
                 Ksrc + (size_t)kr * KVSTR + dq * 4);
            int d = f >> 4, kq = f & 15;
            cp16(vb + swz((uint32_t)(((kq >> 3) * 128 + d) * 128 + (kq & 7) * 16)),
                 Vsrc + (size_t)d * Tn + kq * 4);
        }
        CP_COMMIT();
    };

    const int a_r  = (lane & 7) + ((lane >> 3) & 1) * 8;
    const int a_kc = lane >> 4;
    const int b_r  = (lane & 7) + (lane >> 4) * 8;
    const int b_kc = (lane >> 3) & 1;
    const int g    = lane >> 2;
    const int cq2  = (lane & 3) * 2;
    const float scale2 = 0.08838834764831843f * 1.4426950408889634f; // 1/sqrt(hd) * log2(e)

    float o[16][4];
#pragma unroll
    for (int nt = 0; nt < 16; nt++)
#pragma unroll
        for (int q = 0; q < 4; q++) o[nt][q] = 0.f;
    float m0 = -1e30f, m1 = -1e30f, l0 = 0.f, l1 = 0.f;

    kv_issue(0);

    for (int kt = 0; kt < nkt; kt++) {
        __syncthreads();                       // prev compute done (buffers free)
        if (kt + 1 < nkt) { kv_issue(kt + 1); CP_WAIT(1); }
        else              { CP_WAIT(0); }
        __syncthreads();                       // tiles visible to all warps

        uint32_t kb = base + 65536u + (uint32_t)(kt & 1) * 65536u;
        uint32_t vb = kb + 32768u;

        // ---- S = Q @ K^T  (warp: 16 rows x 64 keys)
        float sacc[8][4];
#pragma unroll
        for (int nt = 0; nt < 8; nt++)
#pragma unroll
            for (int q = 0; q < 4; q++) sacc[nt][q] = 0.f;

#pragma unroll
        for (int ks = 0; ks < 16; ks++) {
            uint32_t af[4];
            ldsm_x4(af, base + swz((uint32_t)((((ks >> 2) * 128 + wid * 16 + a_r) * 128)
                                              + ((ks & 3) * 2 + a_kc) * 16)));
            uint32_t bf[8][2];
#pragma unroll
            for (int np = 0; np < 4; np++) {
                uint32_t tmp[4];
                ldsm_x4(tmp, kb + swz((uint32_t)((((ks >> 2) * 64 + np * 16 + b_r) * 128)
                                                 + ((ks & 3) * 2 + b_kc) * 16)));
                bf[np * 2][0] = tmp[0]; bf[np * 2][1] = tmp[1];
                bf[np * 2 + 1][0] = tmp[2]; bf[np * 2 + 1][1] = tmp[3];
            }
#pragma unroll
            for (int nt = 0; nt < 8; nt++) mma_tf32(sacc[nt], af, bf[nt]);
        }

        // ---- scale (into exp2 domain) + causal mask
        if (kt >= 2 * qb) {
            int rl0 = wid * 16 + g, rl1 = rl0 + 8;
            int kbl = (kt - 2 * qb) * 64;
#pragma unroll
            for (int nt = 0; nt < 8; nt++) {
                int kc0 = kbl + nt * 8 + cq2;
                sacc[nt][0] = (kc0     > rl0) ? -1e30f : sacc[nt][0] * scale2;
                sacc[nt][1] = (kc0 + 1 > rl0) ? -1e30f : sacc[nt][1] * scale2;
                sacc[nt][2] = (kc0     > rl1) ? -1e30f : sacc[nt][2] * scale2;
                sacc[nt][3] = (kc0 + 1 > rl1) ? -1e30f : sacc[nt][3] * scale2;
            }
        } else {
#pragma unroll
            for (int nt = 0; nt < 8; nt++)
#pragma unroll
                for (int q = 0; q < 4; q++) sacc[nt][q] *= scale2;
        }

        // ---- online softmax (rows g and g+8; reduce over quad lanes)
        float mx0 = -1e30f, mx1 = -1e30f;
#pragma unroll
        for (int nt = 0; nt < 8; nt++) {
            mx0 = fmaxf(mx0, fmaxf(sacc[nt][0], sacc[nt][1]));
            mx1 = fmaxf(mx1, fmaxf(sacc[nt][2], sacc[nt][3]));
        }
        mx0 = fmaxf(mx0, __shfl_xor_sync(0xffffffffu, mx0, 1));
        mx0 = fmaxf(mx0, __shfl_xor_sync(0xffffffffu, mx0, 2));
        mx1 = fmaxf(mx1, __shfl_xor_sync(0xffffffffu, mx1, 1));
        mx1 = fmaxf(mx1, __shfl_xor_sync(0xffffffffu, mx1, 2));
        float nm0 = fmaxf(m0, mx0), nm1 = fmaxf(m1, mx1);
        float al0 = exp2f(m0 - nm0), al1 = exp2f(m1 - nm1);
        float s0 = 0.f, s1 = 0.f;
#pragma unroll
        for (int nt = 0; nt < 8; nt++) {
            sacc[nt][0] = exp2f(sacc[nt][0] - nm0);
            sacc[nt][1] = exp2f(sacc[nt][1] - nm0);
            sacc[nt][2] = exp2f(sacc[nt][2] - nm1);
            sacc[nt][3] = exp2f(sacc[nt][3] - nm1);
            s0 += sacc[nt][0] + sacc[nt][1];
            s1 += sacc[nt][2] + sacc[nt][3];
        }
        s0 += __shfl_xor_sync(0xffffffffu, s0, 1);
        s0 += __shfl_xor_sync(0xffffffffu, s0, 2);
        s1 += __shfl_xor_sync(0xffffffffu, s1, 1);
        s1 += __shfl_xor_sync(0xffffffffu, s1, 2);
        l0 = l0 * al0 + s0; l1 = l1 * al1 + s1;
        m0 = nm0; m1 = nm1;

        // ---- rescale O accum
#pragma unroll
        for (int nt = 0; nt < 16; nt++) {
            o[nt][0] *= al0; o[nt][1] *= al0;
            o[nt][2] *= al1; o[nt][3] *= al1;
        }

        // ---- store P (tf32-rounded) to smem; warp-private rows
        uint32_t pb = base + 196608u;
#pragma unroll
        for (int nt = 0; nt < 8; nt++) {
            int col = nt * 8 + cq2;
            uint32_t o0 = swz((uint32_t)((((col >> 5) * 128 + wid * 16 + g) * 128) + (col & 31) * 4));
            sts64(pb + o0, f2tf32(sacc[nt][0]), f2tf32(sacc[nt][1]));
            uint32_t o1 = swz((uint32_t)((((col >> 5) * 128 + wid * 16 + g + 8) * 128) + (col & 31) * 4));
            sts64(pb + o1, f2tf32(sacc[nt][2]), f2tf32(sacc[nt][3]));
        }
        __syncwarp();

        // ---- O += P @ V  (warp: 16 rows x 128 d)
#pragma unroll
        for (int ks = 0; ks < 8; ks++) {
            uint32_t af[4];
            ldsm_x4(af, pb + swz((uint32_t)((((ks >> 2) * 128 + wid * 16 + a_r) * 128)
                                            + ((ks & 3) * 2 + a_kc) * 16)));
#pragma unroll
            for (int np = 0; np < 8; np++) {
                uint32_t tmp[4];
                ldsm_x4(tmp, vb + swz((uint32_t)((((ks >> 2) * 128 + np * 16 + b_r) * 128)
                                                 + ((ks & 3) * 2 + b_kc) * 16)));
                mma_tf32(o[np * 2],     af, tmp);
                mma_tf32(o[np * 2 + 1], af, tmp + 2);
            }
        }
    }

    // ---- epilogue: O /= l, round to tf32, write [row][h*HD + col]
    float il0 = 1.f / l0, il1 = 1.f / l1;
    float* Ob = Og + ((size_t)(b * Tn + qb * FM + wid * 16)) * DMODEL + h * HD;
#pragma unroll
    for (int nt = 0; nt < 16; nt++) {
        int col = nt * 8 + cq2;
        uint2 w0 = make_uint2(f2tf32(o[nt][0] * il0), f2tf32(o[nt][1] * il0));
        uint2 w1 = make_uint2(f2tf32(o[nt][2] * il1), f2tf32(o[nt][3] * il1));
        *(uint2*)(Ob + (size_t)g * DMODEL + col)       = w0;
        *(uint2*)(Ob + (size_t)(g + 8) * DMODEL + col) = w1;
    }
}

// ---------------- launch ----------------
extern "C" void kernel_launch(void* const* d_in, const int* in_sizes, int n_in,
                              void* d_out, int out_size) {
    (void)in_sizes; (void)n_in; (void)out_size;
    const float* x  = (const float*)d_in[0];
    const float* wq = (const float*)d_in[1];
    const float* wk = (const float*)d_in[2];
    const float* wv = (const float*)d_in[3];
    const float* wo = (const float*)d_in[4];
    float* out = (float*)d_out;

    float *xr, *Q, *KV, *VT, *O, *wqT, *wkvT, *woT;
    cudaGetSymbolAddress((void**)&xr,   g_xr);
    cudaGetSymbolAddress((void**)&Q,    g_Q);
    cudaGetSymbolAddress((void**)&KV,   g_KV);
    cudaGetSymbolAddress((void**)&VT,   g_VT);
    cudaGetSymbolAddress((void**)&O,    g_O);
    cudaGetSymbolAddress((void**)&wqT,  g_wqT);
    cudaGetSymbolAddress((void**)&wkvT, g_wkvT);
    cudaGetSymbolAddress((void**)&woT,  g_woT);

    cudaFuncSetAttribute(flash_mma, cudaFuncAttributeMaxDynamicSharedMemorySize, FLASH_SMEM);
    cudaFuncSetAttribute(gemm_mma,  cudaFuncAttributeMaxDynamicSharedMemorySize, GEMM_SMEM);

    invf_kernel<<<1, 64>>>();

    // Weights: transpose to [N,K] K-major + tf32 rounding
    transpose_rna<<<dim3(DMODEL / 32, GK / 32), dim3(32, 8)>>>(wq, wqT, GK, DMODEL);
    transpose_rna<<<dim3(KVDIM  / 32, GK / 32), dim3(32, 8)>>>(wk, wkvT, GK, KVDIM);
    transpose_rna<<<dim3(KVDIM  / 32, GK / 32), dim3(32, 8)>>>(wv, wkvT + (size_t)KVDIM * GK, GK, KVDIM);
    transpose_rna<<<dim3(DMODEL / 32, GK / 32), dim3(32, 8)>>>(wo, woT, GK, DMODEL);

    // Activations: tf32 rounding
    {
        int n4 = ROWS * DMODEL / 4;
        round_rna_vec<<<(n4 + 255) / 256, 256>>>(x, xr, n4);
    }

    // Projections (tensor cores)
    gemm_mma<<<dim3(DMODEL / BN, ROWS / BM), 256, GEMM_SMEM>>>(xr, wqT,  Q,  DMODEL);
    gemm_mma<<<dim3(KVSTR  / BN, ROWS / BM), 256, GEMM_SMEM>>>(xr, wkvT, KV, KVSTR);

    // RoPE on Q and K (rounded outputs)
    {
        int totq = ROWS * NH * 64;
        rope_kernel<<<(totq + 255) / 256, 256>>>(Q, NH, DMODEL, totq);
        int totk = ROWS * NKV * 64;
        rope_kernel<<<(totk + 255) / 256, 256>>>(KV, NKV, KVSTR, totk);
    }

    // V transpose (rounded) for the PV mma B operand
    vtrans_kernel<<<dim3(Tn / 32, HD / 32, Bn * NKV), dim3(32, 8)>>>(KV, VT);

    // Causal attention on tensor cores
    flash_mma<<<dim3(Tn / FM, NH, Bn), 256, FLASH_SMEM>>>(Q, KV, VT, O);

    // Output projection
    gemm_mma<<<dim3(DMODEL / BN, ROWS / BM), 256, GEMM_SMEM>>>(O, woT, out, DMODEL);
}

// round 5
// speedup vs baseline: 4.0410x; 1.1320x over previous
#include <cuda_runtime.h>
#include <math.h>
#include <stdint.h>

// ---------------- problem constants ----------------
#define Bn 2
#define Tn 2048
#define NH 16
#define NKV 4
#define HD 128
#define DMODEL 2048
#define KVDIM 512
#define QKVSTR 3072         // combined QKV row: Q[0:2048) K[2048:2560) V[2560:3072)
#define ROWS 4096           // Bn*Tn
#define GK 2048             // K dim of every GEMM

// ---------------- scratch (__device__ globals) ----------------
__device__ float g_xr  [(size_t)ROWS * DMODEL];   // tf32-rounded x
__device__ float g_QKV [(size_t)ROWS * QKVSTR];   // fused projections
__device__ float g_VT  [(size_t)ROWS * KVDIM];    // V transposed: [b][kvh][d][t]
__device__ float g_O   [(size_t)ROWS * DMODEL];   // flash output, tf32-rounded
__device__ float g_wT  [(size_t)QKVSTR * GK];     // fused [wq;wk;wv] [N,K] K-major, rounded
__device__ float g_woT [(size_t)DMODEL * GK];
__device__ float g_invf[64];

// ---------------- PTX helpers (baseline sm_80+ only) ----------------
__device__ __forceinline__ uint32_t smem_u32(const void* p) {
    uint32_t a;
    asm("{ .reg .u64 t; cvta.to.shared.u64 t, %1; cvt.u32.u64 %0, t; }" : "=r"(a) : "l"(p));
    return a;
}
__device__ __forceinline__ uint32_t f2tf32(float x) {
    uint32_t r; asm("cvt.rna.tf32.f32 %0, %1;" : "=r"(r) : "f"(x)); return r;
}
__device__ __forceinline__ uint32_t swz(uint32_t off) {   // SW128: bits[6:4] ^= bits[9:7]
    return off ^ ((off >> 3) & 0x70);
}
__device__ __forceinline__ void cp16(uint32_t dst, const void* src) {
    asm volatile("cp.async.cg.shared.global [%0], [%1], 16;" :: "r"(dst), "l"(src) : "memory");
}
#define CP_COMMIT() asm volatile("cp.async.commit_group;" ::: "memory")
#define CP_WAIT(n)  asm volatile("cp.async.wait_group %0;" :: "n"(n) : "memory")

__device__ __forceinline__ void ldsm_x4(uint32_t* r, uint32_t addr) {
    asm volatile("ldmatrix.sync.aligned.m8n8.x4.shared.b16 {%0,%1,%2,%3}, [%4];"
                 : "=r"(r[0]), "=r"(r[1]), "=r"(r[2]), "=r"(r[3]) : "r"(addr));
}
__device__ __forceinline__ void mma_tf32(float* d, const uint32_t* a, const uint32_t* b) {
    asm volatile(
        "mma.sync.aligned.m16n8k8.row.col.f32.tf32.tf32.f32 "
        "{%0,%1,%2,%3}, {%4,%5,%6,%7}, {%8,%9}, {%0,%1,%2,%3};"
        : "+f"(d[0]), "+f"(d[1]), "+f"(d[2]), "+f"(d[3])
        : "r"(a[0]), "r"(a[1]), "r"(a[2]), "r"(a[3]), "r"(b[0]), "r"(b[1]));
}
#define STS128(r0, r1, r2, r3, smem_addr) \
    asm volatile("st.shared.v4.b32 [%0], {%1, %2, %3, %4};" \
        :: "r"(smem_addr), "r"(r0), "r"(r1), "r"(r2), "r"(r3) : "memory")
__device__ __forceinline__ void sts64(uint32_t addr, uint32_t a, uint32_t b) {
    asm volatile("st.shared.v2.b32 [%0], {%1,%2};" :: "r"(addr), "r"(a), "r"(b) : "memory");
}

// ---------------- misc small kernels ----------------
__global__ void invf_kernel() {
    int d = threadIdx.x;
    if (d < 64) g_invf[d] = (float)exp(-((double)d / 64.0) * log(10000.0));
}

// out[n*K + k] = round_tf32(in[k*N + n]);  grid (N/32, K/32), block (32,8)
__global__ void transpose_rna(const float* __restrict__ in, float* __restrict__ out, int K, int N) {
    __shared__ float t[32][33];
    int n0 = blockIdx.x * 32, k0 = blockIdx.y * 32;
#pragma unroll
    for (int i = threadIdx.y; i < 32; i += 8)
        t[i][threadIdx.x] = in[(size_t)(k0 + i) * N + n0 + threadIdx.x];
    __syncthreads();
#pragma unroll
    for (int i = threadIdx.y; i < 32; i += 8)
        out[(size_t)(n0 + i) * K + k0 + threadIdx.x] = __uint_as_float(f2tf32(t[threadIdx.x][i]));
}

// V transpose: g_QKV V-cols [b*Tn+t][2560 + kvh*HD + d] -> g_VT[(b*NKV+kvh)*HD + d][t]
__global__ void vtrans_kernel(const float* __restrict__ QKV, float* __restrict__ VT) {
    __shared__ float t[32][33];
    int bk = blockIdx.z;
    int b = bk >> 2, kvh = bk & 3;
    const float* src = QKV + ((size_t)b * Tn) * QKVSTR + 2560 + kvh * HD;
    float* dst = VT + (size_t)bk * HD * Tn;
    int t0 = blockIdx.x * 32, d0 = blockIdx.y * 32;
#pragma unroll
    for (int i = threadIdx.y; i < 32; i += 8)
        t[i][threadIdx.x] = src[(size_t)(t0 + i) * QKVSTR + d0 + threadIdx.x];
    __syncthreads();
#pragma unroll
    for (int i = threadIdx.y; i < 32; i += 8)
        dst[(size_t)(d0 + i) * Tn + t0 + threadIdx.x] = __uint_as_float(f2tf32(t[threadIdx.x][i]));
}

// elementwise tf32 rounding, vectorized
__global__ void round_rna_vec(const float* __restrict__ in, float* __restrict__ out, int n4) {
    int i = blockIdx.x * blockDim.x + threadIdx.x;
    if (i < n4) {
        float4 v = ((const float4*)in)[i];
        uint4 r = make_uint4(f2tf32(v.x), f2tf32(v.y), f2tf32(v.z), f2tf32(v.w));
        ((uint4*)out)[i] = r;
    }
}

// RoPE in-place on a head-block inside g_QKV; outputs tf32-rounded
__global__ void rope_kernel(float* __restrict__ X, int nheads, int total) {
    int idx = blockIdx.x * blockDim.x + threadIdx.x;
    if (idx >= total) return;
    int d    = idx & 63;
    int rest = idx >> 6;
    int hh   = rest % nheads;
    int row  = rest / nheads;
    int t    = row & (Tn - 1);
    float ang = (float)t * g_invf[d];
    float sn, cs;
    sincosf(ang, &sn, &cs);
    float* p = X + (size_t)row * QKVSTR + hh * HD + d;
    float x0 = p[0], x1 = p[64];
    p[0]  = __uint_as_float(f2tf32(x0 * cs - x1 * sn));
    p[64] = __uint_as_float(f2tf32(x1 * cs + x0 * sn));
}

// ---------------- tf32 mma.sync GEMM v2 ----------------
// C[M,N] = A[M,2048] @ Bt[N,2048]^T.  Block 128x256, BK=32, 3-stage cp.async,
// 8 warps (2 rows x 4 cols), warp tile 64x64, one __syncthreads per k-iter.
#define BM 128
#define BN 256
#define BK 32
#define NSTG 3
#define ASTG 16384            // 128 rows x 128B
#define BSTG 32768            // 256 rows x 128B
#define STG  (ASTG + BSTG)
#define GEMM_SMEM (NSTG * STG)
#define KITERS (GK / BK)      // 64

__global__ __launch_bounds__(256, 1)
void gemm_mma(const float* __restrict__ A, const float* __restrict__ Bt,
              float* __restrict__ C, int N) {
    extern __shared__ char dsm[];
    const uint32_t base = smem_u32(dsm);

    const int tid  = threadIdx.x;
    const int wid  = tid >> 5;
    const int lane = tid & 31;
    const int mb   = blockIdx.y * BM;
    const int nb   = blockIdx.x * BN;
    const int wm   = (wid & 1) * 64;
    const int wn   = (wid >> 1) * 64;

    const float* Ag = A  + (size_t)mb * GK;
    const float* Bg = Bt + (size_t)nb * GK;

    float acc[4][8][4];
#pragma unroll
    for (int mt = 0; mt < 4; mt++)
#pragma unroll
        for (int nt = 0; nt < 8; nt++)
#pragma unroll
            for (int q = 0; q < 4; q++) acc[mt][nt][q] = 0.f;

    // cp.async mapping: 16B chunks; A has 1024 chunks, B has 2048.
    auto issue = [&](int buf, int s) {
        uint32_t sa = base + (uint32_t)buf * STG;
        uint32_t sb = sa + ASTG;
        int k0 = s * BK;
#pragma unroll
        for (int i = 0; i < 4; i++) {
            int cc  = tid + i * 256;
            int row = cc >> 3, kc = cc & 7;
            cp16(sa + swz((uint32_t)(row * 128 + kc * 16)),
                 Ag + (size_t)row * GK + k0 + kc * 4);
        }
#pragma unroll
        for (int i = 0; i < 8; i++) {
            int cc  = tid + i * 256;
            int row = cc >> 3, kc = cc & 7;
            cp16(sb + swz((uint32_t)(row * 128 + kc * 16)),
                 Bg + (size_t)row * GK + k0 + kc * 4);
        }
        CP_COMMIT();
    };

    issue(0, 0); issue(1, 1);

    const int a_r  = (lane & 7) + ((lane >> 3) & 1) * 8;
    const int a_kc = (lane >> 4);
    const int b_r  = (lane & 7) + (lane >> 4) * 8;
    const int b_kc = ((lane >> 3) & 1);

    int st = 0, stp = 2;
    for (int s = 0; s < KITERS; s++) {
        if (s + 2 < KITERS) CP_WAIT(1); else CP_WAIT(0);
        __syncthreads();
        if (s + 2 < KITERS) issue(stp, s + 2);

        uint32_t sa = base + (uint32_t)st * STG + (uint32_t)(wm * 128);
        uint32_t sb = base + (uint32_t)st * STG + ASTG + (uint32_t)(wn * 128);

#pragma unroll
        for (int ks = 0; ks < 4; ks++) {
            uint32_t afr[4][4];
            uint32_t bfr[8][2];
#pragma unroll
            for (int mt = 0; mt < 4; mt++)
                ldsm_x4(afr[mt], sa + swz((uint32_t)((mt * 16 + a_r) * 128 + (2 * ks + a_kc) * 16)));
#pragma unroll
            for (int np = 0; np < 4; np++) {
                uint32_t tmp[4];
                ldsm_x4(tmp, sb + swz((uint32_t)((np * 16 + b_r) * 128 + (2 * ks + b_kc) * 16)));
                bfr[np * 2][0] = tmp[0]; bfr[np * 2][1] = tmp[1];
                bfr[np * 2 + 1][0] = tmp[2]; bfr[np * 2 + 1][1] = tmp[3];
            }
#pragma unroll
            for (int mt = 0; mt < 4; mt++)
#pragma unroll
                for (int nt = 0; nt < 8; nt++)
                    mma_tf32(acc[mt][nt], afr[mt], bfr[nt]);
        }
        st  = (st  == NSTG - 1) ? 0 : st + 1;
        stp = (stp == NSTG - 1) ? 0 : stp + 1;
    }

    const int g = lane >> 2;
    const int cq = (lane & 3) * 2;
#pragma unroll
    for (int mt = 0; mt < 4; mt++) {
        int row0 = mb + wm + mt * 16 + g;
#pragma unroll
        for (int nt = 0; nt < 8; nt++) {
            int col = nb + wn + nt * 8 + cq;
            *(float2*)(C + (size_t)row0 * N + col)       = make_float2(acc[mt][nt][0], acc[mt][nt][1]);
            *(float2*)(C + (size_t)(row0 + 8) * N + col) = make_float2(acc[mt][nt][2], acc[mt][nt][3]);
        }
    }
}

// ---------------- flash attention on mma.sync tf32 (R4 core, QKV layout) ----
#define FM 128
#define FN 64
#define FLASH_SMEM 229376

__global__ __launch_bounds__(256, 1)
void flash_mma(const float* __restrict__ QKV, const float* __restrict__ VT,
               float* __restrict__ Og) {
    extern __shared__ float sm[];
    const uint32_t base = smem_u32(sm);
    const int tid = threadIdx.x, wid = tid >> 5, lane = tid & 31;
    const int qb = (Tn / FM - 1) - blockIdx.x;   // heavy blocks first
    const int h = blockIdx.y, b = blockIdx.z;
    const int kvh = h >> 2;
    const int nkt = 2 * qb + 2;

    const float* Qg  = QKV + ((size_t)(b * Tn + qb * FM)) * QKVSTR + h * HD;
    const float* Kg  = QKV + ((size_t)(b * Tn)) * QKVSTR + 2048 + kvh * HD;
    const float* Vtg = VT + ((size_t)(b * NKV + kvh)) * HD * Tn;

    // ---- load Q tile (128 x 128)
#pragma unroll
    for (int i = 0; i < 16; i++) {
        int f = tid + i * 256;
        int qr = f >> 5, dq = f & 31;
        float4 v = *(const float4*)(Qg + (size_t)qr * QKVSTR + dq * 4);
        uint32_t off = swz((uint32_t)(((dq >> 3) * 128 + qr) * 128 + (dq & 7) * 16));
        STS128(__float_as_uint(v.x), __float_as_uint(v.y),
               __float_as_uint(v.z), __float_as_uint(v.w), base + off);
    }

    auto kv_issue = [&](int kt) {
        uint32_t kb = base + 65536u + (uint32_t)(kt & 1) * 65536u;
        uint32_t vb = kb + 32768u;
        const float* Ksrc = Kg  + (size_t)(kt * FN) * QKVSTR;
        const float* Vsrc = Vtg + kt * FN;
#pragma unroll
        for (int i = 0; i < 8; i++) {
            int f = tid + i * 256;
            int kr = f >> 5, dq = f & 31;
            cp16(kb + swz((uint32_t)(((dq >> 3) * 64 + kr) * 128 + (dq & 7) * 16)),
                 Ksrc + (size_t)kr * QKVSTR + dq * 4);
            int d = f >> 4, kq = f & 15;
            cp16(vb + swz((uint32_t)(((kq >> 3) * 128 + d) * 128 + (kq & 7) * 16)),
                 Vsrc + (size_t)d * Tn + kq * 4);
        }
        CP_COMMIT();
    };

    const int a_r  = (lane & 7) + ((lane >> 3) & 1) * 8;
    const int a_kc = lane >> 4;
    const int b_r  = (lane & 7) + (lane >> 4) * 8;
    const int b_kc = (lane >> 3) & 1;
    const int g    = lane >> 2;
    const int cq2  = (lane & 3) * 2;
    const float scale2 = 0.08838834764831843f * 1.4426950408889634f;

    float o[16][4];
#pragma unroll
    for (int nt = 0; nt < 16; nt++)
#pragma unroll
        for (int q = 0; q < 4; q++) o[nt][q] = 0.f;
    float m0 = -1e30f, m1 = -1e30f, l0 = 0.f, l1 = 0.f;

    kv_issue(0);

    for (int kt = 0; kt < nkt; kt++) {
        __syncthreads();
        if (kt + 1 < nkt) { kv_issue(kt + 1); CP_WAIT(1); }
        else              { CP_WAIT(0); }
        __syncthreads();

        uint32_t kb = base + 65536u + (uint32_t)(kt & 1) * 65536u;
        uint32_t vb = kb + 32768u;

        // ---- S = Q @ K^T
        float sacc[8][4];
#pragma unroll
        for (int nt = 0; nt < 8; nt++)
#pragma unroll
            for (int q = 0; q < 4; q++) sacc[nt][q] = 0.f;

#pragma unroll
        for (int ks = 0; ks < 16; ks++) {
            uint32_t af[4];
            ldsm_x4(af, base + swz((uint32_t)((((ks >> 2) * 128 + wid * 16 + a_r) * 128)
                                              + ((ks & 3) * 2 + a_kc) * 16)));
            uint32_t bf[8][2];
#pragma unroll
            for (int np = 0; np < 4; np++) {
                uint32_t tmp[4];
                ldsm_x4(tmp, kb + swz((uint32_t)((((ks >> 2) * 64 + np * 16 + b_r) * 128)
                                                 + ((ks & 3) * 2 + b_kc) * 16)));
                bf[np * 2][0] = tmp[0]; bf[np * 2][1] = tmp[1];
                bf[np * 2 + 1][0] = tmp[2]; bf[np * 2 + 1][1] = tmp[3];
            }
#pragma unroll
            for (int nt = 0; nt < 8; nt++) mma_tf32(sacc[nt], af, bf[nt]);
        }

        // ---- scale + causal mask
        if (kt >= 2 * qb) {
            int rl0 = wid * 16 + g, rl1 = rl0 + 8;
            int kbl = (kt - 2 * qb) * 64;
#pragma unroll
            for (int nt = 0; nt < 8; nt++) {
                int kc0 = kbl + nt * 8 + cq2;
                sacc[nt][0] = (kc0     > rl0) ? -1e30f : sacc[nt][0] * scale2;
                sacc[nt][1] = (kc0 + 1 > rl0) ? -1e30f : sacc[nt][1] * scale2;
                sacc[nt][2] = (kc0     > rl1) ? -1e30f : sacc[nt][2] * scale2;
                sacc[nt][3] = (kc0 + 1 > rl1) ? -1e30f : sacc[nt][3] * scale2;
            }
        } else {
#pragma unroll
            for (int nt = 0; nt < 8; nt++)
#pragma unroll
                for (int q = 0; q < 4; q++) sacc[nt][q] *= scale2;
        }

        // ---- online softmax
        float mx0 = -1e30f, mx1 = -1e30f;
#pragma unroll
        for (int nt = 0; nt < 8; nt++) {
            mx0 = fmaxf(mx0, fmaxf(sacc[nt][0], sacc[nt][1]));
            mx1 = fmaxf(mx1, fmaxf(sacc[nt][2], sacc[nt][3]));
        }
        mx0 = fmaxf(mx0, __shfl_xor_sync(0xffffffffu, mx0, 1));
        mx0 = fmaxf(mx0, __shfl_xor_sync(0xffffffffu, mx0, 2));
        mx1 = fmaxf(mx1, __shfl_xor_sync(0xffffffffu, mx1, 1));
        mx1 = fmaxf(mx1, __shfl_xor_sync(0xffffffffu, mx1, 2));
        float nm0 = fmaxf(m0, mx0), nm1 = fmaxf(m1, mx1);
        float al0 = exp2f(m0 - nm0), al1 = exp2f(m1 - nm1);
        float s0 = 0.f, s1 = 0.f;
#pragma unroll
        for (int nt = 0; nt < 8; nt++) {
            sacc[nt][0] = exp2f(sacc[nt][0] - nm0);
            sacc[nt][1] = exp2f(sacc[nt][1] - nm0);
            sacc[nt][2] = exp2f(sacc[nt][2] - nm1);
            sacc[nt][3] = exp2f(sacc[nt][3] - nm1);
            s0 += sacc[nt][0] + sacc[nt][1];
            s1 += sacc[nt][2] + sacc[nt][3];
        }
        s0 += __shfl_xor_sync(0xffffffffu, s0, 1);
        s0 += __shfl_xor_sync(0xffffffffu, s0, 2);
        s1 += __shfl_xor_sync(0xffffffffu, s1, 1);
        s1 += __shfl_xor_sync(0xffffffffu, s1, 2);
        l0 = l0 * al0 + s0; l1 = l1 * al1 + s1;
        m0 = nm0; m1 = nm1;

#pragma unroll
        for (int nt = 0; nt < 16; nt++) {
            o[nt][0] *= al0; o[nt][1] *= al0;
            o[nt][2] *= al1; o[nt][3] *= al1;
        }

        // ---- store P to smem
        uint32_t pb = base + 196608u;
#pragma unroll
        for (int nt = 0; nt < 8; nt++) {
            int col = nt * 8 + cq2;
            uint32_t o0 = swz((uint32_t)((((col >> 5) * 128 + wid * 16 + g) * 128) + (col & 31) * 4));
            sts64(pb + o0, f2tf32(sacc[nt][0]), f2tf32(sacc[nt][1]));
            uint32_t o1 = swz((uint32_t)((((col >> 5) * 128 + wid * 16 + g + 8) * 128) + (col & 31) * 4));
            sts64(pb + o1, f2tf32(sacc[nt][2]), f2tf32(sacc[nt][3]));
        }
        __syncwarp();

        // ---- O += P @ V
#pragma unroll
        for (int ks = 0; ks < 8; ks++) {
            uint32_t af[4];
            ldsm_x4(af, pb + swz((uint32_t)((((ks >> 2) * 128 + wid * 16 + a_r) * 128)
                                            + ((ks & 3) * 2 + a_kc) * 16)));
#pragma unroll
            for (int np = 0; np < 8; np++) {
                uint32_t tmp[4];
                ldsm_x4(tmp, vb + swz((uint32_t)((((ks >> 2) * 128 + np * 16 + b_r) * 128)
                                                 + ((ks & 3) * 2 + b_kc) * 16)));
                mma_tf32(o[np * 2],     af, tmp);
                mma_tf32(o[np * 2 + 1], af, tmp + 2);
            }
        }
    }

    // ---- epilogue
    float il0 = 1.f / l0, il1 = 1.f / l1;
    float* Ob = Og + ((size_t)(b * Tn + qb * FM + wid * 16)) * DMODEL + h * HD;
#pragma unroll
    for (int nt = 0; nt < 16; nt++) {
        int col = nt * 8 + cq2;
        uint2 w0 = make_uint2(f2tf32(o[nt][0] * il0), f2tf32(o[nt][1] * il0));
        uint2 w1 = make_uint2(f2tf32(o[nt][2] * il1), f2tf32(o[nt][3] * il1));
        *(uint2*)(Ob + (size_t)g * DMODEL + col)       = w0;
        *(uint2*)(Ob + (size_t)(g + 8) * DMODEL + col) = w1;
    }
}

// ---------------- launch ----------------
extern "C" void kernel_launch(void* const* d_in, const int* in_sizes, int n_in,
                              void* d_out, int out_size) {
    (void)in_sizes; (void)n_in; (void)out_size;
    const float* x  = (const float*)d_in[0];
    const float* wq = (const float*)d_in[1];
    const float* wk = (const float*)d_in[2];
    const float* wv = (const float*)d_in[3];
    const float* wo = (const float*)d_in[4];
    float* out = (float*)d_out;

    float *xr, *QKV, *VT, *O, *wT, *woT;
    cudaGetSymbolAddress((void**)&xr,  g_xr);
    cudaGetSymbolAddress((void**)&QKV, g_QKV);
    cudaGetSymbolAddress((void**)&VT,  g_VT);
    cudaGetSymbolAddress((void**)&O,   g_O);
    cudaGetSymbolAddress((void**)&wT,  g_wT);
    cudaGetSymbolAddress((void**)&woT, g_woT);

    cudaFuncSetAttribute(flash_mma, cudaFuncAttributeMaxDynamicSharedMemorySize, FLASH_SMEM);
    cudaFuncSetAttribute(gemm_mma,  cudaFuncAttributeMaxDynamicSharedMemorySize, GEMM_SMEM);

    invf_kernel<<<1, 64>>>();

    // Weights: transpose to [N,K] K-major + tf32 rounding; fused [wq;wk;wv]
    transpose_rna<<<dim3(DMODEL / 32, GK / 32), dim3(32, 8)>>>(wq, wT, GK, DMODEL);
    transpose_rna<<<dim3(KVDIM  / 32, GK / 32), dim3(32, 8)>>>(wk, wT + (size_t)2048 * GK, GK, KVDIM);
    transpose_rna<<<dim3(KVDIM  / 32, GK / 32), dim3(32, 8)>>>(wv, wT + (size_t)2560 * GK, GK, KVDIM);
    transpose_rna<<<dim3(DMODEL / 32, GK / 32), dim3(32, 8)>>>(wo, woT, GK, DMODEL);

    // Activations: tf32 rounding
    {
        int n4 = ROWS * DMODEL / 4;
        round_rna_vec<<<(n4 + 255) / 256, 256>>>(x, xr, n4);
    }

    // Fused QKV projection (one GEMM, N=3072)
    gemm_mma<<<dim3(QKVSTR / BN, ROWS / BM), 256, GEMM_SMEM>>>(xr, wT, QKV, QKVSTR);

    // RoPE on Q and K heads inside QKV
    {
        int totq = ROWS * NH * 64;
        rope_kernel<<<(totq + 255) / 256, 256>>>(QKV, NH, totq);
        int totk = ROWS * NKV * 64;
        rope_kernel<<<(totk + 255) / 256, 256>>>(QKV + 2048, NKV, totk);
    }

    // V transpose for the PV mma B operand
    vtrans_kernel<<<dim3(Tn / 32, HD / 32, Bn * NKV), dim3(32, 8)>>>(QKV, VT);

    // Causal attention on tensor cores
    flash_mma<<<dim3(Tn / FM, NH, Bn), 256, FLASH_SMEM>>>(QKV, VT, O);

    // Output projection
    gemm_mma<<<dim3(DMODEL / BN, ROWS / BM), 256, GEMM_SMEM>>>(O, woT, out, DMODEL);
}

// round 6
// speedup vs baseline: 4.0921x; 1.0127x over previous
#include <cuda_runtime.h>
#include <math.h>
#include <stdint.h>

// ---------------- problem constants ----------------
#define Bn 2
#define Tn 2048
#define NH 16
#define NKV 4
#define HD 128
#define DMODEL 2048
#define KVDIM 512
#define QKVSTR 3072         // combined QKV row: Q[0:2048) K[2048:2560) V[2560:3072)
#define ROWS 4096           // Bn*Tn
#define GK 2048             // K dim of every GEMM

// ---------------- scratch (__device__ globals) ----------------
__device__ float g_xr  [(size_t)ROWS * DMODEL];   // tf32-rounded x
__device__ float g_QKV [(size_t)ROWS * QKVSTR];   // fused projections
__device__ float g_VT  [(size_t)ROWS * KVDIM];    // V transposed: [b][kvh][d][t]
__device__ float g_O   [(size_t)ROWS * DMODEL];   // flash output, tf32-rounded
__device__ float g_wT  [(size_t)QKVSTR * GK];     // fused [wq;wk;wv] [N,K] K-major, rounded
__device__ float g_woT [(size_t)DMODEL * GK];
__device__ float g_invf[64];

// ---------------- PTX helpers (baseline sm_80+ only) ----------------
__device__ __forceinline__ uint32_t smem_u32(const void* p) {
    uint32_t a;
    asm("{ .reg .u64 t; cvta.to.shared.u64 t, %1; cvt.u32.u64 %0, t; }" : "=r"(a) : "l"(p));
    return a;
}
__device__ __forceinline__ uint32_t f2tf32(float x) {
    uint32_t r; asm("cvt.rna.tf32.f32 %0, %1;" : "=r"(r) : "f"(x)); return r;
}
__device__ __forceinline__ uint32_t swz(uint32_t off) {   // SW128: bits[6:4] ^= bits[9:7]
    return off ^ ((off >> 3) & 0x70);
}
__device__ __forceinline__ void cp16(uint32_t dst, const void* src) {
    asm volatile("cp.async.cg.shared.global [%0], [%1], 16;" :: "r"(dst), "l"(src) : "memory");
}
#define CP_COMMIT() asm volatile("cp.async.commit_group;" ::: "memory")
#define CP_WAIT(n)  asm volatile("cp.async.wait_group %0;" :: "n"(n) : "memory")

__device__ __forceinline__ void ldsm_x4(uint32_t* r, uint32_t addr) {
    asm volatile("ldmatrix.sync.aligned.m8n8.x4.shared.b16 {%0,%1,%2,%3}, [%4];"
                 : "=r"(r[0]), "=r"(r[1]), "=r"(r[2]), "=r"(r[3]) : "r"(addr));
}
__device__ __forceinline__ void mma_tf32(float* d, const uint32_t* a, const uint32_t* b) {
    asm volatile(
        "mma.sync.aligned.m16n8k8.row.col.f32.tf32.tf32.f32 "
        "{%0,%1,%2,%3}, {%4,%5,%6,%7}, {%8,%9}, {%0,%1,%2,%3};"
        : "+f"(d[0]), "+f"(d[1]), "+f"(d[2]), "+f"(d[3])
        : "r"(a[0]), "r"(a[1]), "r"(a[2]), "r"(a[3]), "r"(b[0]), "r"(b[1]));
}
#define STS128(r0, r1, r2, r3, smem_addr) \
    asm volatile("st.shared.v4.b32 [%0], {%1, %2, %3, %4};" \
        :: "r"(smem_addr), "r"(r0), "r"(r1), "r"(r2), "r"(r3) : "memory")
__device__ __forceinline__ void sts64(uint32_t addr, uint32_t a, uint32_t b) {
    asm volatile("st.shared.v2.b32 [%0], {%1,%2};" :: "r"(addr), "r"(a), "r"(b) : "memory");
}

// ---------------- misc small kernels ----------------
__global__ void invf_kernel() {
    int d = threadIdx.x;
    if (d < 64) g_invf[d] = (float)exp(-((double)d / 64.0) * log(10000.0));
}

// All 4 weight transposes in one launch.
// grid.x ranges: [0,64) wq, [64,80) wk, [80,96) wv, [96,160) wo; grid.y = 64 k-blocks.
__global__ void transpose_all(const float* __restrict__ wq, const float* __restrict__ wk,
                              const float* __restrict__ wv, const float* __restrict__ wo,
                              float* __restrict__ wT, float* __restrict__ woT) {
    __shared__ float t[32][33];
    int bx = blockIdx.x;
    const float* src; float* dst; int N;
    if (bx < 64)       { src = wq; dst = wT;                         N = 2048; }
    else if (bx < 80)  { src = wk; dst = wT + (size_t)2048 * GK;     N = 512;  bx -= 64; }
    else if (bx < 96)  { src = wv; dst = wT + (size_t)2560 * GK;     N = 512;  bx -= 80; }
    else               { src = wo; dst = woT;                        N = 2048; bx -= 96; }
    int n0 = bx * 32, k0 = blockIdx.y * 32;
#pragma unroll
    for (int i = threadIdx.y; i < 32; i += 8)
        t[i][threadIdx.x] = src[(size_t)(k0 + i) * N + n0 + threadIdx.x];
    __syncthreads();
#pragma unroll
    for (int i = threadIdx.y; i < 32; i += 8)
        dst[(size_t)(n0 + i) * GK + k0 + threadIdx.x] = __uint_as_float(f2tf32(t[threadIdx.x][i]));
}

// V transpose: g_QKV V-cols [b*Tn+t][2560 + kvh*HD + d] -> g_VT[(b*NKV+kvh)*HD + d][t]
__global__ void vtrans_kernel(const float* __restrict__ QKV, float* __restrict__ VT) {
    __shared__ float t[32][33];
    int bk = blockIdx.z;
    int b = bk >> 2, kvh = bk & 3;
    const float* src = QKV + ((size_t)b * Tn) * QKVSTR + 2560 + kvh * HD;
    float* dst = VT + (size_t)bk * HD * Tn;
    int t0 = blockIdx.x * 32, d0 = blockIdx.y * 32;
#pragma unroll
    for (int i = threadIdx.y; i < 32; i += 8)
        t[i][threadIdx.x] = src[(size_t)(t0 + i) * QKVSTR + d0 + threadIdx.x];
    __syncthreads();
#pragma unroll
    for (int i = threadIdx.y; i < 32; i += 8)
        dst[(size_t)(d0 + i) * Tn + t0 + threadIdx.x] = __uint_as_float(f2tf32(t[threadIdx.x][i]));
}

// elementwise tf32 rounding, vectorized
__global__ void round_rna_vec(const float* __restrict__ in, float* __restrict__ out, int n4) {
    int i = blockIdx.x * blockDim.x + threadIdx.x;
    if (i < n4) {
        float4 v = ((const float4*)in)[i];
        uint4 r = make_uint4(f2tf32(v.x), f2tf32(v.y), f2tf32(v.z), f2tf32(v.w));
        ((uint4*)out)[i] = r;
    }
}

// RoPE on Q and K heads of g_QKV in one launch; outputs tf32-rounded.
#define ROPE_TOTQ (ROWS * NH * 64)
#define ROPE_TOTK (ROWS * NKV * 64)
__global__ void rope_all(float* __restrict__ QKV) {
    int idx = blockIdx.x * blockDim.x + threadIdx.x;
    float* base; int nheads;
    if (idx < ROPE_TOTQ) { base = QKV; nheads = NH; }
    else if (idx < ROPE_TOTQ + ROPE_TOTK) { idx -= ROPE_TOTQ; base = QKV + 2048; nheads = NKV; }
    else return;
    int d    = idx & 63;
    int rest = idx >> 6;
    int hh   = rest % nheads;
    int row  = rest / nheads;
    int t    = row & (Tn - 1);
    float ang = (float)t * g_invf[d];
    float sn, cs;
    sincosf(ang, &sn, &cs);
    float* p = base + (size_t)row * QKVSTR + hh * HD + d;
    float x0 = p[0], x1 = p[64];
    p[0]  = __uint_as_float(f2tf32(x0 * cs - x1 * sn));
    p[64] = __uint_as_float(f2tf32(x1 * cs + x0 * sn));
}

// ---------------- tf32 mma.sync GEMM v3 ----------------
// C[M,N] = A[M,2048] @ Bt[N,2048]^T.  Block 128x256, BK=64, 2-stage double
// buffer, 8 warps (2x4), warp tile 64x64, one __syncthreads per k-iter.
// Smem tile layout: [kc(2)][rows][32 floats], 128B sub-rows, swz.
#define BM 128
#define BN 256
#define BK 64
#define NSTG 2
#define ASTG 32768            // 2 * 128 rows * 128B
#define BSTG 65536            // 2 * 256 rows * 128B
#define STG  (ASTG + BSTG)
#define GEMM_SMEM (NSTG * STG)   // 196608
#define KITERS (GK / BK)      // 32

__global__ __launch_bounds__(256, 1)
void gemm_mma(const float* __restrict__ A, const float* __restrict__ Bt,
              float* __restrict__ C, int N) {
    extern __shared__ char dsm[];
    const uint32_t base = smem_u32(dsm);

    const int tid  = threadIdx.x;
    const int wid  = tid >> 5;
    const int lane = tid & 31;
    const int mb   = blockIdx.y * BM;
    const int nb   = blockIdx.x * BN;
    const int wm   = (wid & 1) * 64;
    const int wn   = (wid >> 1) * 64;

    const float* Ag = A  + (size_t)mb * GK;
    const float* Bg = Bt + (size_t)nb * GK;

    float acc[4][8][4];
#pragma unroll
    for (int mt = 0; mt < 4; mt++)
#pragma unroll
        for (int nt = 0; nt < 8; nt++)
#pragma unroll
            for (int q = 0; q < 4; q++) acc[mt][nt][q] = 0.f;

    // cp.async: 16B chunks; rows have 16 chunks (64 floats) split into 2 kc blocks.
    auto issue = [&](int buf, int s) {
        uint32_t sa = base + (uint32_t)buf * STG;
        uint32_t sb = sa + ASTG;
        int k0 = s * BK;
#pragma unroll
        for (int i = 0; i < 8; i++) {          // A: 2048 chunks
            int cc  = tid + i * 256;
            int row = cc >> 4, ch = cc & 15;
            cp16(sa + swz((uint32_t)((ch >> 3) * 16384 + row * 128 + (ch & 7) * 16)),
                 Ag + (size_t)row * GK + k0 + ch * 4);
        }
#pragma unroll
        for (int i = 0; i < 16; i++) {         // B: 4096 chunks
            int cc  = tid + i * 256;
            int row = cc >> 4, ch = cc & 15;
            cp16(sb + swz((uint32_t)((ch >> 3) * 32768 + row * 128 + (ch & 7) * 16)),
                 Bg + (size_t)row * GK + k0 + ch * 4);
        }
        CP_COMMIT();
    };

    issue(0, 0);

    const int a_r  = (lane & 7) + ((lane >> 3) & 1) * 8;
    const int a_kc = (lane >> 4);
    const int b_r  = (lane & 7) + (lane >> 4) * 8;
    const int b_kc = ((lane >> 3) & 1);

    for (int s = 0; s < KITERS; s++) {
        CP_WAIT(0);
        __syncthreads();
        if (s + 1 < KITERS) issue((s + 1) & 1, s + 1);

        uint32_t sa = base + (uint32_t)(s & 1) * STG;
        uint32_t sb = sa + ASTG;

#pragma unroll
        for (int ks = 0; ks < 8; ks++) {
            uint32_t afr[4][4];
            uint32_t bfr[8][2];
            uint32_t akoff = (uint32_t)((ks >> 2) * 16384 + ((ks & 3) * 2 + a_kc) * 16);
            uint32_t bkoff = (uint32_t)((ks >> 2) * 32768 + ((ks & 3) * 2 + b_kc) * 16);
#pragma unroll
            for (int mt = 0; mt < 4; mt++)
                ldsm_x4(afr[mt], sa + swz(akoff + (wm + mt * 16 + a_r) * 128));
#pragma unroll
            for (int np = 0; np < 4; np++) {
                uint32_t tmp[4];
                ldsm_x4(tmp, sb + swz(bkoff + (wn + np * 16 + b_r) * 128));
                bfr[np * 2][0] = tmp[0]; bfr[np * 2][1] = tmp[1];
                bfr[np * 2 + 1][0] = tmp[2]; bfr[np * 2 + 1][1] = tmp[3];
            }
#pragma unroll
            for (int mt = 0; mt < 4; mt++)
#pragma unroll
                for (int nt = 0; nt < 8; nt++)
                    mma_tf32(acc[mt][nt], afr[mt], bfr[nt]);
        }
    }

    const int g = lane >> 2;
    const int cq = (lane & 3) * 2;
#pragma unroll
    for (int mt = 0; mt < 4; mt++) {
        int row0 = mb + wm + mt * 16 + g;
#pragma unroll
        for (int nt = 0; nt < 8; nt++) {
            int col = nb + wn + nt * 8 + cq;
            *(float2*)(C + (size_t)row0 * N + col)       = make_float2(acc[mt][nt][0], acc[mt][nt][1]);
            *(float2*)(C + (size_t)(row0 + 8) * N + col) = make_float2(acc[mt][nt][2], acc[mt][nt][3]);
        }
    }
}

// ---------------- flash attention on mma.sync tf32 (unchanged core) --------
#define FM 128
#define FN 64
#define FLASH_SMEM 229376

__global__ __launch_bounds__(256, 1)
void flash_mma(const float* __restrict__ QKV, const float* __restrict__ VT,
               float* __restrict__ Og) {
    extern __shared__ float sm[];
    const uint32_t base = smem_u32(sm);
    const int tid = threadIdx.x, wid = tid >> 5, lane = tid & 31;
    const int qb = (Tn / FM - 1) - blockIdx.x;   // heavy blocks first
    const int h = blockIdx.y, b = blockIdx.z;
    const int kvh = h >> 2;
    const int nkt = 2 * qb + 2;

    const float* Qg  = QKV + ((size_t)(b * Tn + qb * FM)) * QKVSTR + h * HD;
    const float* Kg  = QKV + ((size_t)(b * Tn)) * QKVSTR + 2048 + kvh * HD;
    const float* Vtg = VT + ((size_t)(b * NKV + kvh)) * HD * Tn;

    // ---- load Q tile (128 x 128)
#pragma unroll
    for (int i = 0; i < 16; i++) {
        int f = tid + i * 256;
        int qr = f >> 5, dq = f & 31;
        float4 v = *(const float4*)(Qg + (size_t)qr * QKVSTR + dq * 4);
        uint32_t off = swz((uint32_t)(((dq >> 3) * 128 + qr) * 128 + (dq & 7) * 16));
        STS128(__float_as_uint(v.x), __float_as_uint(v.y),
               __float_as_uint(v.z), __float_as_uint(v.w), base + off);
    }

    auto kv_issue = [&](int kt) {
        uint32_t kb = base + 65536u + (uint32_t)(kt & 1) * 65536u;
        uint32_t vb = kb + 32768u;
        const float* Ksrc = Kg  + (size_t)(kt * FN) * QKVSTR;
        const float* Vsrc = Vtg + kt * FN;
#pragma unroll
        for (int i = 0; i < 8; i++) {
            int f = tid + i * 256;
            int kr = f >> 5, dq = f & 31;
            cp16(kb + swz((uint32_t)(((dq >> 3) * 64 + kr) * 128 + (dq & 7) * 16)),
                 Ksrc + (size_t)kr * QKVSTR + dq * 4);
            int d = f >> 4, kq = f & 15;
            cp16(vb + swz((uint32_t)(((kq >> 3) * 128 + d) * 128 + (kq & 7) * 16)),
                 Vsrc + (size_t)d * Tn + kq * 4);
        }
        CP_COMMIT();
    };

    const int a_r  = (lane & 7) + ((lane >> 3) & 1) * 8;
    const int a_kc = lane >> 4;
    const int b_r  = (lane & 7) + (lane >> 4) * 8;
    const int b_kc = (lane >> 3) & 1;
    const int g    = lane >> 2;
    const int cq2  = (lane & 3) * 2;
    const float scale2 = 0.08838834764831843f * 1.4426950408889634f;

    float o[16][4];
#pragma unroll
    for (int nt = 0; nt < 16; nt++)
#pragma unroll
        for (int q = 0; q < 4; q++) o[nt][q] = 0.f;
    float m0 = -1e30f, m1 = -1e30f, l0 = 0.f, l1 = 0.f;

    kv_issue(0);

    for (int kt = 0; kt < nkt; kt++) {
        __syncthreads();
        if (kt + 1 < nkt) { kv_issue(kt + 1); CP_WAIT(1); }
        else              { CP_WAIT(0); }
        __syncthreads();

        uint32_t kb = base + 65536u + (uint32_t)(kt & 1) * 65536u;
        uint32_t vb = kb + 32768u;

        // ---- S = Q @ K^T
        float sacc[8][4];
#pragma unroll
        for (int nt = 0; nt < 8; nt++)
#pragma unroll
            for (int q = 0; q < 4; q++) sacc[nt][q] = 0.f;

#pragma unroll
        for (int ks = 0; ks < 16; ks++) {
            uint32_t af[4];
            ldsm_x4(af, base + swz((uint32_t)((((ks >> 2) * 128 + wid * 16 + a_r) * 128)
                                              + ((ks & 3) * 2 + a_kc) * 16)));
            uint32_t bf[8][2];
#pragma unroll
            for (int np = 0; np < 4; np++) {
                uint32_t tmp[4];
                ldsm_x4(tmp, kb + swz((uint32_t)((((ks >> 2) * 64 + np * 16 + b_r) * 128)
                                                 + ((ks & 3) * 2 + b_kc) * 16)));
                bf[np * 2][0] = tmp[0]; bf[np * 2][1] = tmp[1];
                bf[np * 2 + 1][0] = tmp[2]; bf[np * 2 + 1][1] = tmp[3];
            }
#pragma unroll
            for (int nt = 0; nt < 8; nt++) mma_tf32(sacc[nt], af, bf[nt]);
        }

        // ---- scale + causal mask
        if (kt >= 2 * qb) {
            int rl0 = wid * 16 + g, rl1 = rl0 + 8;
            int kbl = (kt - 2 * qb) * 64;
#pragma unroll
            for (int nt = 0; nt < 8; nt++) {
                int kc0 = kbl + nt * 8 + cq2;
                sacc[nt][0] = (kc0     > rl0) ? -1e30f : sacc[nt][0] * scale2;
                sacc[nt][1] = (kc0 + 1 > rl0) ? -1e30f : sacc[nt][1] * scale2;
                sacc[nt][2] = (kc0     > rl1) ? -1e30f : sacc[nt][2] * scale2;
                sacc[nt][3] = (kc0 + 1 > rl1) ? -1e30f : sacc[nt][3] * scale2;
            }
        } else {
#pragma unroll
            for (int nt = 0; nt < 8; nt++)
#pragma unroll
                for (int q = 0; q < 4; q++) sacc[nt][q] *= scale2;
        }

        // ---- online softmax
        float mx0 = -1e30f, mx1 = -1e30f;
#pragma unroll
        for (int nt = 0; nt < 8; nt++) {
            mx0 = fmaxf(mx0, fmaxf(sacc[nt][0], sacc[nt][1]));
            mx1 = fmaxf(mx1, fmaxf(sacc[nt][2], sacc[nt][3]));
        }
        mx0 = fmaxf(mx0, __shfl_xor_sync(0xffffffffu, mx0, 1));
        mx0 = fmaxf(mx0, __shfl_xor_sync(0xffffffffu, mx0, 2));
        mx1 = fmaxf(mx1, __shfl_xor_sync(0xffffffffu, mx1, 1));
        mx1 = fmaxf(mx1, __shfl_xor_sync(0xffffffffu, mx1, 2));
        float nm0 = fmaxf(m0, mx0), nm1 = fmaxf(m1, mx1);
        float al0 = exp2f(m0 - nm0), al1 = exp2f(m1 - nm1);
        float s0 = 0.f, s1 = 0.f;
#pragma unroll
        for (int nt = 0; nt < 8; nt++) {
            sacc[nt][0] = exp2f(sacc[nt][0] - nm0);
            sacc[nt][1] = exp2f(sacc[nt][1] - nm0);
            sacc[nt][2] = exp2f(sacc[nt][2] - nm1);
            sacc[nt][3] = exp2f(sacc[nt][3] - nm1);
            s0 += sacc[nt][0] + sacc[nt][1];
            s1 += sacc[nt][2] + sacc[nt][3];
        }
        s0 += __shfl_xor_sync(0xffffffffu, s0, 1);
        s0 += __shfl_xor_sync(0xffffffffu, s0, 2);
        s1 += __shfl_xor_sync(0xffffffffu, s1, 1);
        s1 += __shfl_xor_sync(0xffffffffu, s1, 2);
        l0 = l0 * al0 + s0; l1 = l1 * al1 + s1;
        m0 = nm0; m1 = nm1;

#pragma unroll
        for (int nt = 0; nt < 16; nt++) {
            o[nt][0] *= al0; o[nt][1] *= al0;
            o[nt][2] *= al1; o[nt][3] *= al1;
        }

        // ---- store P to smem
        uint32_t pb = base + 196608u;
#pragma unroll
        for (int nt = 0; nt < 8; nt++) {
            int col = nt * 8 + cq2;
            uint32_t o0 = swz((uint32_t)((((col >> 5) * 128 + wid * 16 + g) * 128) + (col & 31) * 4));
            sts64(pb + o0, f2tf32(sacc[nt][0]), f2tf32(sacc[nt][1]));
            uint32_t o1 = swz((uint32_t)((((col >> 5) * 128 + wid * 16 + g + 8) * 128) + (col & 31) * 4));
            sts64(pb + o1, f2tf32(sacc[nt][2]), f2tf32(sacc[nt][3]));
        }
        __syncwarp();

        // ---- O += P @ V
#pragma unroll
        for (int ks = 0; ks < 8; ks++) {
            uint32_t af[4];
            ldsm_x4(af, pb + swz((uint32_t)((((ks >> 2) * 128 + wid * 16 + a_r) * 128)
                                            + ((ks & 3) * 2 + a_kc) * 16)));
#pragma unroll
            for (int np = 0; np < 8; np++) {
                uint32_t tmp[4];
                ldsm_x4(tmp, vb + swz((uint32_t)((((ks >> 2) * 128 + np * 16 + b_r) * 128)
                                                 + ((ks & 3) * 2 + b_kc) * 16)));
                mma_tf32(o[np * 2],     af, tmp);
                mma_tf32(o[np * 2 + 1], af, tmp + 2);
            }
        }
    }

    // ---- epilogue
    float il0 = 1.f / l0, il1 = 1.f / l1;
    float* Ob = Og + ((size_t)(b * Tn + qb * FM + wid * 16)) * DMODEL + h * HD;
#pragma unroll
    for (int nt = 0; nt < 16; nt++) {
        int col = nt * 8 + cq2;
        uint2 w0 = make_uint2(f2tf32(o[nt][0] * il0), f2tf32(o[nt][1] * il0));
        uint2 w1 = make_uint2(f2tf32(o[nt][2] * il1), f2tf32(o[nt][3] * il1));
        *(uint2*)(Ob + (size_t)g * DMODEL + col)       = w0;
        *(uint2*)(Ob + (size_t)(g + 8) * DMODEL + col) = w1;
    }
}

// ---------------- launch ----------------
extern "C" void kernel_launch(void* const* d_in, const int* in_sizes, int n_in,
                              void* d_out, int out_size) {
    (void)in_sizes; (void)n_in; (void)out_size;
    const float* x  = (const float*)d_in[0];
    const float* wq = (const float*)d_in[1];
    const float* wk = (const float*)d_in[2];
    const float* wv = (const float*)d_in[3];
    const float* wo = (const float*)d_in[4];
    float* out = (float*)d_out;

    float *xr, *QKV, *VT, *O, *wT, *woT;
    cudaGetSymbolAddress((void**)&xr,  g_xr);
    cudaGetSymbolAddress((void**)&QKV, g_QKV);
    cudaGetSymbolAddress((void**)&VT,  g_VT);
    cudaGetSymbolAddress((void**)&O,   g_O);
    cudaGetSymbolAddress((void**)&wT,  g_wT);
    cudaGetSymbolAddress((void**)&woT, g_woT);

    cudaFuncSetAttribute(flash_mma, cudaFuncAttributeMaxDynamicSharedMemorySize, FLASH_SMEM);
    cudaFuncSetAttribute(gemm_mma,  cudaFuncAttributeMaxDynamicSharedMemorySize, GEMM_SMEM);

    invf_kernel<<<1, 64>>>();

    // All weight transposes (tf32-rounded, K-major) in one launch
    transpose_all<<<dim3(160, 64), dim3(32, 8)>>>(wq, wk, wv, wo, wT, woT);

    // Activations: tf32 rounding
    {
        int n4 = ROWS * DMODEL / 4;
        round_rna_vec<<<(n4 + 255) / 256, 256>>>(x, xr, n4);
    }

    // Fused QKV projection (one GEMM, N=3072)
    gemm_mma<<<dim3(QKVSTR / BN, ROWS / BM), 256, GEMM_SMEM>>>(xr, wT, QKV, QKVSTR);

    // RoPE on Q and K heads (one launch)
    {
        int tot = ROPE_TOTQ + ROPE_TOTK;
        rope_all<<<(tot + 255) / 256, 256>>>(QKV);
    }

    // V transpose for the PV mma B operand
    vtrans_kernel<<<dim3(Tn / 32, HD / 32, Bn * NKV), dim3(32, 8)>>>(QKV, VT);

    // Causal attention on tensor cores
    flash_mma<<<dim3(Tn / FM, NH, Bn), 256, FLASH_SMEM>>>(QKV, VT, O);

    // Output projection
    gemm_mma<<<dim3(DMODEL / BN, ROWS / BM), 256, GEMM_SMEM>>>(O, woT, out, DMODEL);
}